// round 13
// baseline (speedup 1.0000x reference)
#include <cuda_runtime.h>
#include <cuda_bf16.h>
#include <cstdint>

#define N_NODES   50000
#define N_EDGES   400000
#define E_TOT     (N_EDGES + N_NODES)
#define N_GRAPHS  128
#define D_IN      768
#define D_HID     256
#define NEG_SLOPE 0.2f
#define EPS_COS   1e-8f
#define EPS_BN    1e-5f

#if defined(__CUDA_ARCH_FEAT_SM103_ALL) || defined(__CUDA_ARCH_SPECIFIC__)
#define HAS_TCGEN05 1
#else
#define HAS_TCGEN05 0
#endif

// ---------------- scratch (device globals; no allocation) ----------------
__device__ float    g_rel[N_NODES];
__device__ float    g_bufA[(size_t)N_NODES * D_HID];
__device__ float    g_bufB[(size_t)N_NODES * D_HID];
__device__ float    g_as[N_NODES];
__device__ float    g_ad[N_NODES];
__device__ float    g_bnsum[D_HID];
__device__ float    g_bnsq[D_HID];
__device__ float    g_bnsc[D_HID];
__device__ float    g_bnsh[D_HID];
__device__ float    g_pool[N_GRAPHS * D_HID];
__device__ int      g_cnt[N_GRAPHS];
// CSR (built once, reused by both layers)
__device__ int      g_dcnt[N_NODES];
__device__ int      g_rowoff[N_NODES + 1];
__device__ int      g_wr[N_NODES];
__device__ int      g_srcid[E_TOT];
// pre-swizzled bf16 hi/lo weight images: [ktile64][256 n-rows][128 bytes] SW128
__device__ unsigned char g_w1h[12 * 32768];
__device__ unsigned char g_w1l[12 * 32768];
__device__ unsigned char g_w2h[4 * 32768];
__device__ unsigned char g_w2l[4 * 32768];

// ---------------- PTX helpers ----------------
__device__ __forceinline__ uint32_t elect_one_pred() {
    uint32_t pred;
    asm volatile(
        "{\n\t.reg .pred p;\n\t"
        "elect.sync _|p, 0xFFFFFFFF;\n\t"
        "selp.b32 %0, 1, 0, p;\n\t}"
        : "=r"(pred));
    return pred;
}
__device__ __forceinline__ uint32_t smem_to_u32(const void* p) {
    uint32_t a;
    asm("{ .reg .u64 t; cvta.to.shared.u64 t, %1; cvt.u32.u64 %0, t; }"
        : "=r"(a) : "l"(p));
    return a;
}
#define MBARRIER_INIT(addr, cnt) \
    asm volatile("mbarrier.init.shared.b64 [%0], %1;" :: "r"((uint32_t)(addr)), "r"((uint32_t)(cnt)) : "memory")
#define MBARRIER_EXPECT_TX(addr, bytes) \
    asm volatile("mbarrier.arrive.expect_tx.shared.b64 _, [%0], %1;" \
        :: "r"((uint32_t)(addr)), "r"((uint32_t)(bytes)) : "memory")
#define MBARRIER_WAIT_PARITY(addr, parity) do { \
    uint32_t _m = (uint32_t)(addr); uint32_t _p = (uint32_t)(parity); uint32_t _d; \
    asm volatile("{\n\t.reg .pred p;\n\t" \
        "mbarrier.try_wait.parity.acquire.cta.shared::cta.b64 p, [%1], %2;\n\t" \
        "selp.b32 %0, 1, 0, p;\n\t}" : "=r"(_d) : "r"(_m), "r"(_p) : "memory"); \
    if (!_d) { \
        asm volatile("{\n\t.reg .pred P1;\n\t" \
            "WL_%=:\n\t" \
            "mbarrier.try_wait.parity.acquire.cta.shared::cta.b64 P1, [%0], %1, 0x989680;\n\t" \
            "@P1 bra.uni WD_%=;\n\t" \
            "bra.uni WL_%=;\n\t" \
            "WD_%=:\n\t}" :: "r"(_m), "r"(_p) : "memory"); \
    } \
} while (0)
#define TCGEN05_ALLOC(sa, n) \
    asm volatile("tcgen05.alloc.cta_group::1.sync.aligned.shared::cta.b32 [%0], %1;" \
        :: "r"((uint32_t)(sa)), "r"((uint32_t)(n)) : "memory")
#define TCGEN05_DEALLOC(t, n) \
    asm volatile("tcgen05.dealloc.cta_group::1.sync.aligned.b32 %0, %1;" :: "r"(t), "r"((uint32_t)(n)))
#define TCGEN05_RELINQ() \
    asm volatile("tcgen05.relinquish_alloc_permit.cta_group::1.sync.aligned;")
#define TCGEN05_COMMIT(mb) \
    asm volatile("tcgen05.commit.cta_group::1.mbarrier::arrive::one.shared::cluster.b64 [%0];" \
        :: "r"((uint32_t)(mb)) : "memory")
#define TCGEN05_FENCE_AFTER()  asm volatile("tcgen05.fence::after_thread_sync;" ::: "memory")
#define TCGEN05_FENCE_BEFORE() asm volatile("tcgen05.fence::before_thread_sync;" ::: "memory")
#define TCGEN05_WAIT_LD()      asm volatile("tcgen05.wait::ld.sync.aligned;" ::: "memory")
#define FENCE_ASYNC_SHARED()   asm volatile("fence.proxy.async.shared::cta;" ::: "memory")
#define TCGEN05_LD_X32(r, ta) \
    asm volatile("tcgen05.ld.sync.aligned.32x32b.x32.b32 " \
        "{%0, %1, %2, %3, %4, %5, %6, %7, %8, %9, %10, %11, %12, %13, %14, %15, " \
        " %16, %17, %18, %19, %20, %21, %22, %23, %24, %25, %26, %27, %28, %29, %30, %31}, [%32];" \
        : "=r"((r)[0]), "=r"((r)[1]), "=r"((r)[2]), "=r"((r)[3]), \
          "=r"((r)[4]), "=r"((r)[5]), "=r"((r)[6]), "=r"((r)[7]), \
          "=r"((r)[8]), "=r"((r)[9]), "=r"((r)[10]), "=r"((r)[11]), \
          "=r"((r)[12]), "=r"((r)[13]), "=r"((r)[14]), "=r"((r)[15]), \
          "=r"((r)[16]), "=r"((r)[17]), "=r"((r)[18]), "=r"((r)[19]), \
          "=r"((r)[20]), "=r"((r)[21]), "=r"((r)[22]), "=r"((r)[23]), \
          "=r"((r)[24]), "=r"((r)[25]), "=r"((r)[26]), "=r"((r)[27]), \
          "=r"((r)[28]), "=r"((r)[29]), "=r"((r)[30]), "=r"((r)[31]) \
        : "r"(ta))

static constexpr uint64_t SMEM_DESC_BASE_SW128 =
    (uint64_t(2) << 61) | (uint64_t(1) << 46) | (uint64_t(64) << 32) | (uint64_t(1) << 16);
__device__ __forceinline__ uint64_t make_desc(uint32_t addr) {
    return SMEM_DESC_BASE_SW128 | ((uint64_t)(addr >> 4) & 0x3FFF);
}
// idesc: dtype=F32, atype=btype=BF16, N=256, M=128
#define IDESC_G 0x8400490u

#if HAS_TCGEN05
__device__ __forceinline__ void mma_f16_ss(uint32_t d, uint64_t ad, uint64_t bd,
                                           uint32_t idesc, uint32_t en) {
    asm volatile(
        "{\n\t.reg .pred p;\n\t"
        "setp.ne.u32 p, %5, 0;\n\t"
        "tcgen05.mma.cta_group::1.kind::f16 [%0], %1, %2, %3, {%4, %4, %4, %4}, p;\n\t}"
        :: "r"(d), "l"(ad), "l"(bd), "r"(idesc), "r"(0u), "r"(en) : "memory");
}
__device__ __forceinline__ void bulk_cp(uint32_t dst, const void* src, uint32_t bytes,
                                        uint32_t mb) {
    asm volatile(
        "cp.async.bulk.shared::cta.global.mbarrier::complete_tx::bytes [%0], [%1], %2, [%3];"
        :: "r"(dst), "l"(src), "r"(bytes), "r"(mb) : "memory");
}
#endif

__device__ __forceinline__ float warp_red(float v) {
    #pragma unroll
    for (int o = 16; o; o >>= 1) v += __shfl_xor_sync(0xffffffffu, v, o);
    return v;
}
// packed pair convert: res = bf16(a) | bf16(b)<<16
#define CVT2(res, a_, b_) \
    asm("cvt.rn.bf16x2.f32 %0, %1, %2;" : "=r"(res) : "f"(b_), "f"(a_))

// convert float4 -> packed {hi01, hi23, lo01, lo23}
__device__ __forceinline__ uint4 split_pack(float4 v) {
    uint4 pk;
    CVT2(pk.x, v.x, v.y);
    CVT2(pk.y, v.z, v.w);
    float h0 = __uint_as_float(pk.x << 16);
    float h1 = __uint_as_float(pk.x & 0xFFFF0000u);
    float h2 = __uint_as_float(pk.y << 16);
    float h3 = __uint_as_float(pk.y & 0xFFFF0000u);
    CVT2(pk.z, v.x - h0, v.y - h1);
    CVT2(pk.w, v.z - h2, v.w - h3);
    return pk;
}

// ---------------- kernel bodies (device functions for fusion) ----------------
__device__ void body_prep_w(int blk, const float* __restrict__ W, int K,
                            unsigned char* __restrict__ hi, unsigned char* __restrict__ lo) {
    int idx = blk * 256 + threadIdx.x;
    if (idx >= K * 256) return;
    int k = idx >> 8, n = idx & 255;
    float v = W[idx];
    __nv_bfloat16 h = __float2bfloat16_rn(v);
    __nv_bfloat16 l = __float2bfloat16_rn(v - __bfloat162float(h));
    int kt = k >> 6, kk = k & 63;
    uint32_t off = (uint32_t)(n * 128 + kk * 2);
    off ^= ((off >> 3) & 0x70);
    size_t base = (size_t)kt * 32768 + off;
    *(__nv_bfloat16*)(hi + base) = h;
    *(__nv_bfloat16*)(lo + base) = l;
}

__device__ void body_rel(int blk, const float* __restrict__ claim, const float* __restrict__ x,
                         const int* __restrict__ batch, float* __restrict__ rel,
                         int* __restrict__ cnt) {
    int warp = (blk * 256 + threadIdx.x) >> 5;
    int lane = threadIdx.x & 31;
    if (warp >= N_NODES) return;
    int b = batch[warp];
    const float4* ce = (const float4*)(claim + (size_t)b * D_IN);
    const float4* xv = (const float4*)(x + (size_t)warp * D_IN);
    float dot = 0.f, nc = 0.f, nx = 0.f;
    #pragma unroll
    for (int k = lane; k < D_IN / 4; k += 32) {
        float4 c = ce[k], v = xv[k];
        dot += c.x * v.x + c.y * v.y + c.z * v.z + c.w * v.w;
        nc  += c.x * c.x + c.y * c.y + c.z * c.z + c.w * c.w;
        nx  += v.x * v.x + v.y * v.y + v.z * v.z + v.w * v.w;
    }
    dot = warp_red(dot); nc = warp_red(nc); nx = warp_red(nx);
    if (lane == 0) {
        float nrm = sqrtf(nc) * sqrtf(nx);
        rel[warp] = dot / fmaxf(nrm, EPS_COS);
        atomicAdd(&cnt[b], 1);
    }
}

__device__ void body_hist(int blk, const int* __restrict__ ei, int* __restrict__ dcnt) {
    int i = blk * 256 + threadIdx.x;
    if (i >= E_TOT) return;
    int d = (i < N_EDGES) ? ei[N_EDGES + i] : (i - N_EDGES);
    atomicAdd(&dcnt[d], 1);
}

__device__ void body_fill(int blk, const int* __restrict__ ei, int* __restrict__ wr,
                          int* __restrict__ srcid) {
    int i = blk * 256 + threadIdx.x;
    if (i >= E_TOT) return;
    int s, d;
    if (i < N_EDGES) { s = ei[i]; d = ei[N_EDGES + i]; }
    else { s = d = i - N_EDGES; }
    int pos = atomicAdd(&wr[d], 1);
    srcid[pos] = s;
}

// ---- fused independent kernels (block-range dispatch) ----
#define NODE_BLKS  ((N_NODES + 255) / 256)
#define EDGE_BLKS  ((E_TOT + 255) / 256)
#define WNODE_BLKS ((N_NODES * 32 + 255) / 256)
#define PREP1_BLKS ((D_IN * 256 + 255) / 256)
#define PREP2_BLKS ((D_HID * 256 + 255) / 256)

__global__ void k_misc1(const float* claim, const float* x, const int* batch,
                        float* rel, int* cnt, const int* ei, int* dcnt,
                        const float* W1, unsigned char* w1h, unsigned char* w1l) {
    int b = blockIdx.x;
    if (b < WNODE_BLKS) { body_rel(b, claim, x, batch, rel, cnt); return; }
    b -= WNODE_BLKS;
    if (b < EDGE_BLKS) { body_hist(b, ei, dcnt); return; }
    b -= EDGE_BLKS;
    body_prep_w(b, W1, D_IN, w1h, w1l);
}
__global__ void k_misc2(const int* ei, int* wr, int* srcid,
                        const float* W2, unsigned char* w2h, unsigned char* w2l) {
    int b = blockIdx.x;
    if (b < EDGE_BLKS) { body_fill(b, ei, wr, srcid); return; }
    b -= EDGE_BLKS;
    body_prep_w(b, W2, D_HID, w2h, w2l);
}

// -------- tcgen05 GEMM (R10 config: K=64 single stage, 256 thr, occ=2) ----
#define SM_TPTR 0
#define SM_MBAR 8
#define SM_MBT  16
#define SM_ASV  1024
#define SM_ADV  2048
#define SM_AH   3072
#define SM_AL   (SM_AH + 16384)
#define SM_BH   (SM_AL + 16384)
#define SM_BL   (SM_BH + 32768)
#define SM_SZ   (SM_BL + 32768)

__global__ __launch_bounds__(256, 2) void k_gemm_tc(
    const float* __restrict__ A, int K,
    const unsigned char* __restrict__ Bh, const unsigned char* __restrict__ Bl,
    float* __restrict__ C,
    const float* __restrict__ rowscale,
    const float* __restrict__ colsc, const float* __restrict__ colsh,
    const float* __restrict__ a_s, const float* __restrict__ a_d,
    float* __restrict__ as_out, float* __restrict__ ad_out, int M)
{
#if HAS_TCGEN05
    extern __shared__ char smem[];
    uint32_t sb = smem_to_u32(smem);
    int tid = threadIdx.x, wid = tid >> 5, lane = tid & 31;
    int m0 = blockIdx.x * 128;

    if (tid == 0) { MBARRIER_INIT(sb + SM_MBAR, 1); MBARRIER_INIT(sb + SM_MBT, 1); }
    if (wid == 0) TCGEN05_ALLOC(sb + SM_TPTR, 256);
    float* sAS = (float*)(smem + SM_ASV);
    float* sAD = (float*)(smem + SM_ADV);
    if (tid < 256) { sAS[tid] = a_s[tid]; sAD[tid] = a_d[tid]; }
    __syncthreads();
    uint32_t tmem;
    asm volatile("ld.shared.b32 %0, [%1];" : "=r"(tmem) : "r"(sb + SM_TPTR));
    if (wid == 0) TCGEN05_RELINQ();

    const uint64_t aH = make_desc(sb + SM_AH);
    const uint64_t aL = make_desc(sb + SM_AL);
    const uint64_t bH = make_desc(sb + SM_BH);
    const uint64_t bL = make_desc(sb + SM_BL);

    int rbase = tid >> 4;        // 0..15
    int cq = (tid & 15) << 2;    // 0,4,...,60
    int ph = 0, ph_t = 0;
    const int nk = K >> 6;

    float s_row[8];
    #pragma unroll
    for (int i = 0; i < 8; i++) {
        int gr = m0 + i * 16 + rbase;
        s_row[i] = (rowscale && gr < M) ? rowscale[gr] : 1.0f;
    }
    uint32_t so[8];
    #pragma unroll
    for (int i = 0; i < 8; i++) {
        uint32_t off = (uint32_t)((i * 16 + rbase) * 128 + cq * 2);
        so[i] = off ^ ((off >> 3) & 0x70);
    }

    auto convert_tile = [&](int kt, uint4* pk) {
        int k0 = kt << 6;
        float4 csc = make_float4(1.f, 1.f, 1.f, 1.f);
        float4 csh = make_float4(0.f, 0.f, 0.f, 0.f);
        if (colsc) {
            csc = *(const float4*)(colsc + k0 + cq);
            csh = *(const float4*)(colsh + k0 + cq);
        }
        float4 va[8];
        #pragma unroll
        for (int i = 0; i < 8; i++) {
            int gr = m0 + i * 16 + rbase;
            va[i] = (gr < M) ? *(const float4*)(A + (size_t)gr * K + k0 + cq)
                             : make_float4(0.f, 0.f, 0.f, 0.f);
        }
        #pragma unroll
        for (int i = 0; i < 8; i++) {
            float4 v = va[i];
            float sc = s_row[i];
            v.x *= sc; v.y *= sc; v.z *= sc; v.w *= sc;
            if (colsc) {
                v.x = fmaxf(v.x * csc.x + csh.x, 0.f);
                v.y = fmaxf(v.y * csc.y + csh.y, 0.f);
                v.z = fmaxf(v.z * csc.z + csh.z, 0.f);
                v.w = fmaxf(v.w * csc.w + csh.w, 0.f);
            }
            pk[i] = split_pack(v);
        }
    };

    uint4 pk[8];
    convert_tile(0, pk);

    for (int kt = 0; kt < nk; kt++) {
        if (kt) { MBARRIER_WAIT_PARITY(sb + SM_MBAR, ph); ph ^= 1; }

        if (tid == 0) {
            MBARRIER_EXPECT_TX(sb + SM_MBT, 65536u);
            bulk_cp(sb + SM_BH, Bh + (size_t)kt * 32768, 32768u, sb + SM_MBT);
            bulk_cp(sb + SM_BL, Bl + (size_t)kt * 32768, 32768u, sb + SM_MBT);
        }
        #pragma unroll
        for (int i = 0; i < 8; i++) {
            *(uint2*)(smem + SM_AH + so[i]) = make_uint2(pk[i].x, pk[i].y);
            *(uint2*)(smem + SM_AL + so[i]) = make_uint2(pk[i].z, pk[i].w);
        }
        FENCE_ASYNC_SHARED();
        __syncthreads();
        if (wid == 0) {
            MBARRIER_WAIT_PARITY(sb + SM_MBT, ph_t);
            if (elect_one_pred()) {
                #pragma unroll
                for (int sp = 0; sp < 3; sp++) {
                    uint64_t ad = (sp == 2) ? aL : aH;
                    uint64_t bd = (sp == 1) ? bL : bH;
                    #pragma unroll
                    for (int c = 0; c < 4; c++) {
                        uint32_t en = (kt == 0 && sp == 0 && c == 0) ? 0u : 1u;
                        mma_f16_ss(tmem, ad + c * 2, bd + c * 2, IDESC_G, en);
                    }
                }
                TCGEN05_COMMIT(sb + SM_MBAR);
            }
        }
        ph_t ^= 1;
        if (kt + 1 < nk) convert_tile(kt + 1, pk);
    }
    MBARRIER_WAIT_PARITY(sb + SM_MBAR, ph);
    TCGEN05_FENCE_AFTER();

    if (wid < 4) {
        int row = m0 + wid * 32 + lane;
        float s_acc = 0.f, d_acc = 0.f;
        #pragma unroll
        for (int j = 0; j < 8; j++) {
            uint32_t r[32];
            TCGEN05_LD_X32(r, tmem + j * 32);
            TCGEN05_WAIT_LD();
            #pragma unroll
            for (int q = 0; q < 32; q++) {
                float f = __uint_as_float(r[q]);
                s_acc += f * sAS[j * 32 + q];
                d_acc += f * sAD[j * 32 + q];
            }
            if (row < M) {
                float4* dst = (float4*)(C + (size_t)row * D_HID + j * 32);
                #pragma unroll
                for (int q = 0; q < 8; q++)
                    dst[q] = make_float4(__uint_as_float(r[q * 4 + 0]), __uint_as_float(r[q * 4 + 1]),
                                         __uint_as_float(r[q * 4 + 2]), __uint_as_float(r[q * 4 + 3]));
            }
        }
        if (row < M) { as_out[row] = s_acc; ad_out[row] = d_acc; }
        TCGEN05_FENCE_BEFORE();
    }
    __syncthreads();
    if (tid == 0) {
        asm volatile("mbarrier.inval.shared.b64 [%0];" :: "r"(sb + SM_MBAR) : "memory");
        asm volatile("mbarrier.inval.shared.b64 [%0];" :: "r"(sb + SM_MBT) : "memory");
    }
    __syncthreads();
    if (wid == 0) TCGEN05_DEALLOC(tmem, 256);
#else
    // Correct scalar fallback for the non-arch-specific PTX pass.
    int tid = threadIdx.x;
    if (tid >= 128) return;
    int gr = blockIdx.x * 128 + tid;
    if (gr >= M) return;
    float rs = rowscale ? rowscale[gr] : 1.0f;
    float s_acc = 0.f, d_acc = 0.f;
    for (int n = 0; n < 256; n++) {
        float acc = 0.f;
        for (int k = 0; k < K; k++) {
            int kt = k >> 6, kk = k & 63;
            uint32_t off = (uint32_t)(n * 128 + kk * 2);
            off ^= ((off >> 3) & 0x70);
            float w = __bfloat162float(*(const __nv_bfloat16*)(Bh + (size_t)kt * 32768 + off))
                    + __bfloat162float(*(const __nv_bfloat16*)(Bl + (size_t)kt * 32768 + off));
            float a = A[(size_t)gr * K + k] * rs;
            if (colsc) a = fmaxf(a * colsc[k] + colsh[k], 0.f);
            acc += a * w;
        }
        C[(size_t)gr * 256 + n] = acc;
        s_acc += acc * a_s[n];
        d_acc += acc * a_d[n];
    }
    as_out[gr] = s_acc; ad_out[gr] = d_acc;
#endif
}

// ---------------- zero/init (single launch) ----------------
__global__ void k_zero_all(float* bnsum, float* bnsq, float* pool, int* cnt, int* dcnt) {
    int i = blockIdx.x * blockDim.x + threadIdx.x;
    if (i < N_NODES) dcnt[i] = 0;
    if (i < N_GRAPHS * D_HID) pool[i] = 0.0f;
    if (i < D_HID) { bnsum[i] = 0.0f; bnsq[i] = 0.0f; }
    if (i < N_GRAPHS) cnt[i] = 0;
}

// ---------------- CSR scan ----------------
__global__ __launch_bounds__(1024) void k_scan(const int* __restrict__ dcnt,
                                               int* __restrict__ rowoff,
                                               int* __restrict__ wr) {
    __shared__ int wsum[32];
    int t = threadIdx.x;
    int lane = t & 31, w = t >> 5;
    const int CH = (N_NODES + 1023) / 1024;   // 49
    int lo = t * CH, hi = min(lo + CH, N_NODES);
    int s = 0;
    for (int i = lo; i < hi; i++) s += dcnt[i];
    int inc = s;
    #pragma unroll
    for (int o = 1; o < 32; o <<= 1) {
        int v = __shfl_up_sync(0xffffffffu, inc, o);
        if (lane >= o) inc += v;
    }
    if (lane == 31) wsum[w] = inc;
    __syncthreads();
    if (w == 0) {
        int v = (lane < 32) ? wsum[lane] : 0;
        int wi = v;
        #pragma unroll
        for (int o = 1; o < 32; o <<= 1) {
            int u = __shfl_up_sync(0xffffffffu, wi, o);
            if (lane >= o) wi += u;
        }
        wsum[lane] = wi - v;   // exclusive
        if (lane == 31) rowoff[N_NODES] = wi;
    }
    __syncthreads();
    int run = wsum[w] + inc - s;
    for (int i = lo; i < hi; i++) {
        rowoff[i] = run; wr[i] = run;
        run += dcnt[i];
    }
}

// ---- score helper: attn numerator for edge (s -> d), no max-shift ----
__device__ __forceinline__ float edge_ex(const float* __restrict__ as, float add, int s) {
    float e = __ldg(as + s) + add;
    e = (e > 0.f) ? e : NEG_SLOPE * e;
    return __expf(e);
}

// Warp-cached, software-pipelined CSR gather core. Produces a0/a1 for dst d.
// Pass 1 doubles as edge cache: lane i holds srcid/exp of edge beg+i.
__device__ __forceinline__ void gather_core(
    const float* __restrict__ h,
    const int* __restrict__ rowoff, const int* __restrict__ srcid,
    const float* __restrict__ as, const float* __restrict__ ad,
    int d, int lane, float4& a0, float4& a1)
{
    int beg = rowoff[d], end = rowoff[d + 1];
    float add = ad[d];
    int   s_c = 0;
    float e_c = 0.f;
    if (beg + lane < end) { s_c = srcid[beg + lane]; e_c = edge_ex(as, add, s_c); }
    float part = e_c;
    for (int i = beg + 32 + lane; i < end; i += 32)
        part += edge_ex(as, add, srcid[i]);
    float invden = __frcp_rn(warp_red(part));

    int deg = end - beg;
    int dmain = deg < 32 ? deg : 32;
    a0 = make_float4(0.f, 0.f, 0.f, 0.f);
    a1 = make_float4(0.f, 0.f, 0.f, 0.f);
    // pipelined gather over cached edges (deg <= 32 fast path, MLP=2)
    int s0 = __shfl_sync(0xffffffffu, s_c, 0);
    const float4* hp = (const float4*)(h + (size_t)s0 * D_HID);
    float4 v0 = hp[lane], v1 = hp[lane + 32];
    for (int j = 0; j < dmain; j++) {
        float attn = __shfl_sync(0xffffffffu, e_c, j) * invden;
        float4 w0 = v0, w1 = v1;
        if (j + 1 < dmain) {
            int sn = __shfl_sync(0xffffffffu, s_c, j + 1);
            const float4* hn = (const float4*)(h + (size_t)sn * D_HID);
            v0 = hn[lane]; v1 = hn[lane + 32];
        }
        a0.x += attn * w0.x; a0.y += attn * w0.y; a0.z += attn * w0.z; a0.w += attn * w0.w;
        a1.x += attn * w1.x; a1.y += attn * w1.y; a1.z += attn * w1.z; a1.w += attn * w1.w;
    }
    // slow tail for deg > 32
    for (int i = beg + 32; i < end; i++) {
        int s = srcid[i];
        float attn = edge_ex(as, add, s) * invden;
        const float4* hs = (const float4*)(h + (size_t)s * D_HID);
        float4 w0 = hs[lane], w1 = hs[lane + 32];
        a0.x += attn * w0.x; a0.y += attn * w0.y; a0.z += attn * w0.z; a0.w += attn * w0.w;
        a1.x += attn * w1.x; a1.y += attn * w1.y; a1.z += attn * w1.z; a1.w += attn * w1.w;
    }
}

// ------- fused GAT edge phase (layer 1): softmax + CSR aggregation -------
__global__ void k_agg_fused(const float* __restrict__ h, float* __restrict__ agg,
                            const int* __restrict__ rowoff, const int* __restrict__ srcid,
                            const float* __restrict__ as, const float* __restrict__ ad) {
    int d = (int)(((size_t)blockIdx.x * blockDim.x + threadIdx.x) >> 5);
    int lane = threadIdx.x & 31;
    if (d >= N_NODES) return;
    float4 a0, a1;
    gather_core(h, rowoff, srcid, as, ad, d, lane, a0, a1);
    float4* od = (float4*)(agg + (size_t)d * D_HID);
    od[lane] = a0;
    od[lane + 32] = a1;
}

// ------- fused edge phase (layer 2): softmax + agg + relu(+b2) + mean-pool -------
__global__ void k_agg_pool_fused(const float* __restrict__ h,
                                 const int* __restrict__ rowoff, const int* __restrict__ srcid,
                                 const float* __restrict__ as, const float* __restrict__ ad,
                                 const float* __restrict__ b2,
                                 const int* __restrict__ batch,
                                 float* __restrict__ pool) {
    int d = (int)(((size_t)blockIdx.x * blockDim.x + threadIdx.x) >> 5);
    int lane = threadIdx.x & 31;
    if (d >= N_NODES) return;
    float4 a0, a1;
    gather_core(h, rowoff, srcid, as, ad, d, lane, a0, a1);
    float4 b0 = ((const float4*)b2)[lane];
    float4 b1 = ((const float4*)b2)[lane + 32];
    a0.x = fmaxf(a0.x + b0.x, 0.f); a0.y = fmaxf(a0.y + b0.y, 0.f);
    a0.z = fmaxf(a0.z + b0.z, 0.f); a0.w = fmaxf(a0.w + b0.w, 0.f);
    a1.x = fmaxf(a1.x + b1.x, 0.f); a1.y = fmaxf(a1.y + b1.y, 0.f);
    a1.z = fmaxf(a1.z + b1.z, 0.f); a1.w = fmaxf(a1.w + b1.w, 0.f);
    int g = batch[d];
    float4* pg = (float4*)(pool + (size_t)g * D_HID);
    asm volatile("red.global.add.v4.f32 [%0], {%1,%2,%3,%4};"
                 :: "l"(pg + lane), "f"(a0.x), "f"(a0.y), "f"(a0.z), "f"(a0.w) : "memory");
    asm volatile("red.global.add.v4.f32 [%0], {%1,%2,%3,%4};"
                 :: "l"(pg + lane + 32), "f"(a1.x), "f"(a1.y), "f"(a1.z), "f"(a1.w) : "memory");
}

// ---------------- BatchNorm stats ----------------
#define ROWS_PER_BLK 64
__global__ void k_bnstats(const float* __restrict__ h, float* __restrict__ bsum,
                          float* __restrict__ bsq) {
    int col = threadIdx.x;
    int r0 = blockIdx.x * ROWS_PER_BLK;
    int r1 = min(r0 + ROWS_PER_BLK, N_NODES);
    float s = 0.f, q = 0.f;
    for (int r = r0; r < r1; r++) {
        float v = h[(size_t)r * D_HID + col];
        s += v; q += v * v;
    }
    atomicAdd(&bsum[col], s);
    atomicAdd(&bsq[col], q);
}

// ---------------- BN finalize: per-column scale/shift ----------------
__global__ void k_bnfin(const float* __restrict__ bsum, const float* __restrict__ bsq,
                        const float* __restrict__ gamma, const float* __restrict__ beta,
                        float* __restrict__ sc, float* __restrict__ sh) {
    int col = threadIdx.x;
    float mu = bsum[col] * (1.0f / N_NODES);
    float var = bsq[col] * (1.0f / N_NODES) - mu * mu;
    float s = gamma[col] * rsqrtf(var + EPS_BN);
    sc[col] = s;
    sh[col] = beta[col] - mu * s;
}

// ---------------- classifier ----------------
__global__ void k_clf(const float* __restrict__ pool, const int* __restrict__ cnt,
                      const float* __restrict__ claim, const float* __restrict__ W,
                      const float* __restrict__ bias, float* __restrict__ out) {
    __shared__ float red[256];
    int b = blockIdx.x;
    int t = threadIdx.x;
    float c = fmaxf((float)cnt[b], 1.0f);
    float part = (pool[b * D_HID + t] / c) * W[t];
    #pragma unroll
    for (int j = 0; j < 3; j++) {
        int k = t + j * 256;
        part += claim[(size_t)b * D_IN + k] * W[D_HID + k];
    }
    red[t] = part;
    __syncthreads();
    #pragma unroll
    for (int o = 128; o; o >>= 1) {
        if (t < o) red[t] += red[t + o];
        __syncthreads();
    }
    if (t == 0) out[b] = red[0] + bias[0];
}

// ---------------- host launcher ----------------
extern "C" void kernel_launch(void* const* d_in, const int* in_sizes, int n_in,
                              void* d_out, int out_size) {
    const float* claim   = (const float*)d_in[0];
    const float* x       = (const float*)d_in[1];
    const int*   ei      = (const int*)d_in[2];
    const int*   batch   = (const int*)d_in[3];
    const float* W1      = (const float*)d_in[4];
    const float* a_src1  = (const float*)d_in[5];
    const float* a_dst1  = (const float*)d_in[6];
    // d_in[7] = b1 : provably no-op through training-mode BatchNorm
    const float* W2      = (const float*)d_in[8];
    const float* a_src2  = (const float*)d_in[9];
    const float* a_dst2  = (const float*)d_in[10];
    const float* b2      = (const float*)d_in[11];
    const float* gamma   = (const float*)d_in[12];
    const float* beta    = (const float*)d_in[13];
    const float* clfW    = (const float*)d_in[14];
    const float* clfb    = (const float*)d_in[15];
    float* out = (float*)d_out;

    float *p_rel, *p_A, *p_B, *p_as, *p_ad, *p_bnsum, *p_bnsq, *p_bnsc, *p_bnsh, *p_pool;
    int *p_cnt, *p_dcnt, *p_rowoff, *p_wr, *p_srcid;
    unsigned char *p_w1h, *p_w1l, *p_w2h, *p_w2l;
    cudaGetSymbolAddress((void**)&p_rel, g_rel);
    cudaGetSymbolAddress((void**)&p_A, g_bufA);
    cudaGetSymbolAddress((void**)&p_B, g_bufB);
    cudaGetSymbolAddress((void**)&p_as, g_as);
    cudaGetSymbolAddress((void**)&p_ad, g_ad);
    cudaGetSymbolAddress((void**)&p_bnsum, g_bnsum);
    cudaGetSymbolAddress((void**)&p_bnsq, g_bnsq);
    cudaGetSymbolAddress((void**)&p_bnsc, g_bnsc);
    cudaGetSymbolAddress((void**)&p_bnsh, g_bnsh);
    cudaGetSymbolAddress((void**)&p_pool, g_pool);
    cudaGetSymbolAddress((void**)&p_cnt, g_cnt);
    cudaGetSymbolAddress((void**)&p_dcnt, g_dcnt);
    cudaGetSymbolAddress((void**)&p_rowoff, g_rowoff);
    cudaGetSymbolAddress((void**)&p_wr, g_wr);
    cudaGetSymbolAddress((void**)&p_srcid, g_srcid);
    cudaGetSymbolAddress((void**)&p_w1h, g_w1h);
    cudaGetSymbolAddress((void**)&p_w1l, g_w1l);
    cudaGetSymbolAddress((void**)&p_w2h, g_w2h);
    cudaGetSymbolAddress((void**)&p_w2l, g_w2l);

    cudaFuncSetAttribute(k_gemm_tc, cudaFuncAttributeMaxDynamicSharedMemorySize, SM_SZ);

    const int chunkBlocks = (N_NODES + ROWS_PER_BLK - 1) / ROWS_PER_BLK;
    const int gemmBlocks = (N_NODES + 127) / 128;

    // launch order: GEMM1 stays the 4th launch (ncu captures #4).
    k_zero_all<<<NODE_BLKS, 256>>>(p_bnsum, p_bnsq, p_pool, p_cnt, p_dcnt);
    k_misc1<<<WNODE_BLKS + EDGE_BLKS + PREP1_BLKS, 256>>>(
        claim, x, batch, p_rel, p_cnt, ei, p_dcnt, W1, p_w1h, p_w1l);
    k_scan<<<1, 1024>>>(p_dcnt, p_rowoff, p_wr);
    k_gemm_tc<<<gemmBlocks, 256, SM_SZ>>>(x, D_IN, p_w1h, p_w1l, p_A,
                                          p_rel, nullptr, nullptr,
                                          a_src1, a_dst1, p_as, p_ad, N_NODES);
    k_misc2<<<EDGE_BLKS + PREP2_BLKS, 256>>>(ei, p_wr, p_srcid, W2, p_w2h, p_w2l);

    // ---- layer 1: fused softmax + aggregation ----
    k_agg_fused<<<WNODE_BLKS, 256>>>(p_A, p_B, p_rowoff, p_srcid, p_as, p_ad);

    // ---- BN stats + finalize (apply fused into GEMM2's A-loader) ----
    k_bnstats<<<chunkBlocks, 256>>>(p_B, p_bnsum, p_bnsq);
    k_bnfin<<<1, 256>>>(p_bnsum, p_bnsq, gamma, beta, p_bnsc, p_bnsh);

    // ---- layer 2: GEMM (BN+ReLU fused) + fused edge phase + pooling ----
    k_gemm_tc<<<gemmBlocks, 256, SM_SZ>>>(p_B, D_HID, p_w2h, p_w2l, p_A,
                                          nullptr, p_bnsc, p_bnsh,
                                          a_src2, a_dst2, p_as, p_ad, N_NODES);
    k_agg_pool_fused<<<WNODE_BLKS, 256>>>(p_A, p_rowoff, p_srcid, p_as, p_ad,
                                          b2, batch, p_pool);

    // ---- classifier ----
    k_clf<<<N_GRAPHS, 256>>>(p_pool, p_cnt, claim, clfW, clfb, out);
}

// round 14
// speedup vs baseline: 1.0001x; 1.0001x over previous
#include <cuda_runtime.h>
#include <cuda_bf16.h>
#include <cstdint>

#define N_NODES   50000
#define N_EDGES   400000
#define E_TOT     (N_EDGES + N_NODES)
#define N_GRAPHS  128
#define D_IN      768
#define D_HID     256
#define NEG_SLOPE 0.2f
#define EPS_COS   1e-8f
#define EPS_BN    1e-5f

#if defined(__CUDA_ARCH_FEAT_SM103_ALL) || defined(__CUDA_ARCH_SPECIFIC__)
#define HAS_TCGEN05 1
#else
#define HAS_TCGEN05 0
#endif

// ---------------- scratch (device globals; no allocation) ----------------
__device__ float    g_rel[N_NODES];
__device__ float    g_bufA[(size_t)N_NODES * D_HID];
__device__ float    g_bufB[(size_t)N_NODES * D_HID];
__device__ float    g_as[N_NODES];
__device__ float    g_ad[N_NODES];
__device__ float    g_bnsum[D_HID];
__device__ float    g_bnsq[D_HID];
__device__ float    g_bnsc[D_HID];
__device__ float    g_bnsh[D_HID];
__device__ float    g_pool[N_GRAPHS * D_HID];
__device__ int      g_cnt[N_GRAPHS];
// CSR (built once, reused by both layers)
__device__ int      g_dcnt[N_NODES];
__device__ int      g_rowoff[N_NODES + 1];
__device__ int      g_wr[N_NODES];
__device__ int      g_srcid[E_TOT];
// pre-swizzled bf16 hi/lo weight images: [ktile64][256 n-rows][128 bytes] SW128
__device__ unsigned char g_w1h[12 * 32768];
__device__ unsigned char g_w1l[12 * 32768];
__device__ unsigned char g_w2h[4 * 32768];
__device__ unsigned char g_w2l[4 * 32768];

// ---------------- PTX helpers ----------------
__device__ __forceinline__ uint32_t elect_one_pred() {
    uint32_t pred;
    asm volatile(
        "{\n\t.reg .pred p;\n\t"
        "elect.sync _|p, 0xFFFFFFFF;\n\t"
        "selp.b32 %0, 1, 0, p;\n\t}"
        : "=r"(pred));
    return pred;
}
__device__ __forceinline__ uint32_t smem_to_u32(const void* p) {
    uint32_t a;
    asm("{ .reg .u64 t; cvta.to.shared.u64 t, %1; cvt.u32.u64 %0, t; }"
        : "=r"(a) : "l"(p));
    return a;
}
#define MBARRIER_INIT(addr, cnt) \
    asm volatile("mbarrier.init.shared.b64 [%0], %1;" :: "r"((uint32_t)(addr)), "r"((uint32_t)(cnt)) : "memory")
#define MBARRIER_EXPECT_TX(addr, bytes) \
    asm volatile("mbarrier.arrive.expect_tx.shared.b64 _, [%0], %1;" \
        :: "r"((uint32_t)(addr)), "r"((uint32_t)(bytes)) : "memory")
#define MBARRIER_WAIT_PARITY(addr, parity) do { \
    uint32_t _m = (uint32_t)(addr); uint32_t _p = (uint32_t)(parity); uint32_t _d; \
    asm volatile("{\n\t.reg .pred p;\n\t" \
        "mbarrier.try_wait.parity.acquire.cta.shared::cta.b64 p, [%1], %2;\n\t" \
        "selp.b32 %0, 1, 0, p;\n\t}" : "=r"(_d) : "r"(_m), "r"(_p) : "memory"); \
    if (!_d) { \
        asm volatile("{\n\t.reg .pred P1;\n\t" \
            "WL_%=:\n\t" \
            "mbarrier.try_wait.parity.acquire.cta.shared::cta.b64 P1, [%0], %1, 0x989680;\n\t" \
            "@P1 bra.uni WD_%=;\n\t" \
            "bra.uni WL_%=;\n\t" \
            "WD_%=:\n\t}" :: "r"(_m), "r"(_p) : "memory"); \
    } \
} while (0)
#define TCGEN05_ALLOC(sa, n) \
    asm volatile("tcgen05.alloc.cta_group::1.sync.aligned.shared::cta.b32 [%0], %1;" \
        :: "r"((uint32_t)(sa)), "r"((uint32_t)(n)) : "memory")
#define TCGEN05_DEALLOC(t, n) \
    asm volatile("tcgen05.dealloc.cta_group::1.sync.aligned.b32 %0, %1;" :: "r"(t), "r"((uint32_t)(n)))
#define TCGEN05_RELINQ() \
    asm volatile("tcgen05.relinquish_alloc_permit.cta_group::1.sync.aligned;")
#define TCGEN05_COMMIT(mb) \
    asm volatile("tcgen05.commit.cta_group::1.mbarrier::arrive::one.shared::cluster.b64 [%0];" \
        :: "r"((uint32_t)(mb)) : "memory")
#define TCGEN05_FENCE_AFTER()  asm volatile("tcgen05.fence::after_thread_sync;" ::: "memory")
#define TCGEN05_FENCE_BEFORE() asm volatile("tcgen05.fence::before_thread_sync;" ::: "memory")
#define TCGEN05_WAIT_LD()      asm volatile("tcgen05.wait::ld.sync.aligned;" ::: "memory")
#define FENCE_ASYNC_SHARED()   asm volatile("fence.proxy.async.shared::cta;" ::: "memory")
#define TCGEN05_LD_X32(r, ta) \
    asm volatile("tcgen05.ld.sync.aligned.32x32b.x32.b32 " \
        "{%0, %1, %2, %3, %4, %5, %6, %7, %8, %9, %10, %11, %12, %13, %14, %15, " \
        " %16, %17, %18, %19, %20, %21, %22, %23, %24, %25, %26, %27, %28, %29, %30, %31}, [%32];" \
        : "=r"((r)[0]), "=r"((r)[1]), "=r"((r)[2]), "=r"((r)[3]), \
          "=r"((r)[4]), "=r"((r)[5]), "=r"((r)[6]), "=r"((r)[7]), \
          "=r"((r)[8]), "=r"((r)[9]), "=r"((r)[10]), "=r"((r)[11]), \
          "=r"((r)[12]), "=r"((r)[13]), "=r"((r)[14]), "=r"((r)[15]), \
          "=r"((r)[16]), "=r"((r)[17]), "=r"((r)[18]), "=r"((r)[19]), \
          "=r"((r)[20]), "=r"((r)[21]), "=r"((r)[22]), "=r"((r)[23]), \
          "=r"((r)[24]), "=r"((r)[25]), "=r"((r)[26]), "=r"((r)[27]), \
          "=r"((r)[28]), "=r"((r)[29]), "=r"((r)[30]), "=r"((r)[31]) \
        : "r"(ta))

static constexpr uint64_t SMEM_DESC_BASE_SW128 =
    (uint64_t(2) << 61) | (uint64_t(1) << 46) | (uint64_t(64) << 32) | (uint64_t(1) << 16);
__device__ __forceinline__ uint64_t make_desc(uint32_t addr) {
    return SMEM_DESC_BASE_SW128 | ((uint64_t)(addr >> 4) & 0x3FFF);
}
// idesc: dtype=F32, atype=btype=BF16, N=256, M=128
#define IDESC_G 0x8400490u

#if HAS_TCGEN05
__device__ __forceinline__ void mma_f16_ss(uint32_t d, uint64_t ad, uint64_t bd,
                                           uint32_t idesc, uint32_t en) {
    asm volatile(
        "{\n\t.reg .pred p;\n\t"
        "setp.ne.u32 p, %5, 0;\n\t"
        "tcgen05.mma.cta_group::1.kind::f16 [%0], %1, %2, %3, {%4, %4, %4, %4}, p;\n\t}"
        :: "r"(d), "l"(ad), "l"(bd), "r"(idesc), "r"(0u), "r"(en) : "memory");
}
__device__ __forceinline__ void bulk_cp(uint32_t dst, const void* src, uint32_t bytes,
                                        uint32_t mb) {
    asm volatile(
        "cp.async.bulk.shared::cta.global.mbarrier::complete_tx::bytes [%0], [%1], %2, [%3];"
        :: "r"(dst), "l"(src), "r"(bytes), "r"(mb) : "memory");
}
#endif

__device__ __forceinline__ float warp_red(float v) {
    #pragma unroll
    for (int o = 16; o; o >>= 1) v += __shfl_xor_sync(0xffffffffu, v, o);
    return v;
}
// packed pair convert: res = bf16(a) | bf16(b)<<16
#define CVT2(res, a_, b_) \
    asm("cvt.rn.bf16x2.f32 %0, %1, %2;" : "=r"(res) : "f"(b_), "f"(a_))

// convert float4 -> packed {hi01, hi23, lo01, lo23}
__device__ __forceinline__ uint4 split_pack(float4 v) {
    uint4 pk;
    CVT2(pk.x, v.x, v.y);
    CVT2(pk.y, v.z, v.w);
    float h0 = __uint_as_float(pk.x << 16);
    float h1 = __uint_as_float(pk.x & 0xFFFF0000u);
    float h2 = __uint_as_float(pk.y << 16);
    float h3 = __uint_as_float(pk.y & 0xFFFF0000u);
    CVT2(pk.z, v.x - h0, v.y - h1);
    CVT2(pk.w, v.z - h2, v.w - h3);
    return pk;
}

// ---------------- kernel bodies (device functions for fusion) ----------------
__device__ void body_prep_w(int blk, const float* __restrict__ W, int K,
                            unsigned char* __restrict__ hi, unsigned char* __restrict__ lo) {
    int idx = blk * 256 + threadIdx.x;
    if (idx >= K * 256) return;
    int k = idx >> 8, n = idx & 255;
    float v = W[idx];
    __nv_bfloat16 h = __float2bfloat16_rn(v);
    __nv_bfloat16 l = __float2bfloat16_rn(v - __bfloat162float(h));
    int kt = k >> 6, kk = k & 63;
    uint32_t off = (uint32_t)(n * 128 + kk * 2);
    off ^= ((off >> 3) & 0x70);
    size_t base = (size_t)kt * 32768 + off;
    *(__nv_bfloat16*)(hi + base) = h;
    *(__nv_bfloat16*)(lo + base) = l;
}

__device__ void body_rel(int blk, const float* __restrict__ claim, const float* __restrict__ x,
                         const int* __restrict__ batch, float* __restrict__ rel,
                         int* __restrict__ cnt) {
    int warp = (blk * 256 + threadIdx.x) >> 5;
    int lane = threadIdx.x & 31;
    if (warp >= N_NODES) return;
    int b = batch[warp];
    const float4* ce = (const float4*)(claim + (size_t)b * D_IN);
    const float4* xv = (const float4*)(x + (size_t)warp * D_IN);
    float dot = 0.f, nc = 0.f, nx = 0.f;
    #pragma unroll
    for (int k = lane; k < D_IN / 4; k += 32) {
        float4 c = ce[k], v = xv[k];
        dot += c.x * v.x + c.y * v.y + c.z * v.z + c.w * v.w;
        nc  += c.x * c.x + c.y * c.y + c.z * c.z + c.w * c.w;
        nx  += v.x * v.x + v.y * v.y + v.z * v.z + v.w * v.w;
    }
    dot = warp_red(dot); nc = warp_red(nc); nx = warp_red(nx);
    if (lane == 0) {
        float nrm = sqrtf(nc) * sqrtf(nx);
        rel[warp] = dot / fmaxf(nrm, EPS_COS);
        atomicAdd(&cnt[b], 1);
    }
}

__device__ void body_hist(int blk, const int* __restrict__ ei, int* __restrict__ dcnt) {
    int i = blk * 256 + threadIdx.x;
    if (i >= E_TOT) return;
    int d = (i < N_EDGES) ? ei[N_EDGES + i] : (i - N_EDGES);
    atomicAdd(&dcnt[d], 1);
}

__device__ void body_fill(int blk, const int* __restrict__ ei, int* __restrict__ wr,
                          int* __restrict__ srcid) {
    int i = blk * 256 + threadIdx.x;
    if (i >= E_TOT) return;
    int s, d;
    if (i < N_EDGES) { s = ei[i]; d = ei[N_EDGES + i]; }
    else { s = d = i - N_EDGES; }
    int pos = atomicAdd(&wr[d], 1);
    srcid[pos] = s;
}

// ---- fused independent kernels (block-range dispatch) ----
#define NODE_BLKS  ((N_NODES + 255) / 256)
#define EDGE_BLKS  ((E_TOT + 255) / 256)
#define WNODE_BLKS ((N_NODES * 32 + 255) / 256)
#define WPAIR_BLKS ((((N_NODES + 1) / 2) * 32 + 255) / 256)
#define PREP1_BLKS ((D_IN * 256 + 255) / 256)
#define PREP2_BLKS ((D_HID * 256 + 255) / 256)

__global__ void k_misc1(const float* claim, const float* x, const int* batch,
                        float* rel, int* cnt, const int* ei, int* dcnt,
                        const float* W1, unsigned char* w1h, unsigned char* w1l) {
    int b = blockIdx.x;
    if (b < WNODE_BLKS) { body_rel(b, claim, x, batch, rel, cnt); return; }
    b -= WNODE_BLKS;
    if (b < EDGE_BLKS) { body_hist(b, ei, dcnt); return; }
    b -= EDGE_BLKS;
    body_prep_w(b, W1, D_IN, w1h, w1l);
}
__global__ void k_misc2(const int* ei, int* wr, int* srcid,
                        const float* W2, unsigned char* w2h, unsigned char* w2l) {
    int b = blockIdx.x;
    if (b < EDGE_BLKS) { body_fill(b, ei, wr, srcid); return; }
    b -= EDGE_BLKS;
    body_prep_w(b, W2, D_HID, w2h, w2l);
}

// -------- tcgen05 GEMM (K=64 single stage, 256 thr, occ=2, cvt-in-shadow) ----
#define SM_TPTR 0
#define SM_MBAR 8
#define SM_MBT  16
#define SM_ASV  1024
#define SM_ADV  2048
#define SM_AH   3072
#define SM_AL   (SM_AH + 16384)
#define SM_BH   (SM_AL + 16384)
#define SM_BL   (SM_BH + 32768)
#define SM_SZ   (SM_BL + 32768)

__global__ __launch_bounds__(256, 2) void k_gemm_tc(
    const float* __restrict__ A, int K,
    const unsigned char* __restrict__ Bh, const unsigned char* __restrict__ Bl,
    float* __restrict__ C,
    const float* __restrict__ rowscale,
    const float* __restrict__ colsc, const float* __restrict__ colsh,
    const float* __restrict__ a_s, const float* __restrict__ a_d,
    float* __restrict__ as_out, float* __restrict__ ad_out, int M)
{
#if HAS_TCGEN05
    extern __shared__ char smem[];
    uint32_t sb = smem_to_u32(smem);
    int tid = threadIdx.x, wid = tid >> 5, lane = tid & 31;
    int m0 = blockIdx.x * 128;

    if (tid == 0) { MBARRIER_INIT(sb + SM_MBAR, 1); MBARRIER_INIT(sb + SM_MBT, 1); }
    if (wid == 0) TCGEN05_ALLOC(sb + SM_TPTR, 256);
    float* sAS = (float*)(smem + SM_ASV);
    float* sAD = (float*)(smem + SM_ADV);
    if (tid < 256) { sAS[tid] = a_s[tid]; sAD[tid] = a_d[tid]; }
    __syncthreads();
    uint32_t tmem;
    asm volatile("ld.shared.b32 %0, [%1];" : "=r"(tmem) : "r"(sb + SM_TPTR));
    if (wid == 0) TCGEN05_RELINQ();

    const uint64_t aH = make_desc(sb + SM_AH);
    const uint64_t aL = make_desc(sb + SM_AL);
    const uint64_t bH = make_desc(sb + SM_BH);
    const uint64_t bL = make_desc(sb + SM_BL);

    int rbase = tid >> 4;        // 0..15
    int cq = (tid & 15) << 2;    // 0,4,...,60
    int ph = 0, ph_t = 0;
    const int nk = K >> 6;

    float s_row[8];
    #pragma unroll
    for (int i = 0; i < 8; i++) {
        int gr = m0 + i * 16 + rbase;
        s_row[i] = (rowscale && gr < M) ? rowscale[gr] : 1.0f;
    }
    uint32_t so[8];
    #pragma unroll
    for (int i = 0; i < 8; i++) {
        uint32_t off = (uint32_t)((i * 16 + rbase) * 128 + cq * 2);
        so[i] = off ^ ((off >> 3) & 0x70);
    }

    auto convert_tile = [&](int kt, uint4* pk) {
        int k0 = kt << 6;
        float4 csc = make_float4(1.f, 1.f, 1.f, 1.f);
        float4 csh = make_float4(0.f, 0.f, 0.f, 0.f);
        if (colsc) {
            csc = *(const float4*)(colsc + k0 + cq);
            csh = *(const float4*)(colsh + k0 + cq);
        }
        float4 va[8];
        #pragma unroll
        for (int i = 0; i < 8; i++) {
            int gr = m0 + i * 16 + rbase;
            va[i] = (gr < M) ? *(const float4*)(A + (size_t)gr * K + k0 + cq)
                             : make_float4(0.f, 0.f, 0.f, 0.f);
        }
        #pragma unroll
        for (int i = 0; i < 8; i++) {
            float4 v = va[i];
            float sc = s_row[i];
            v.x *= sc; v.y *= sc; v.z *= sc; v.w *= sc;
            if (colsc) {
                v.x = fmaxf(v.x * csc.x + csh.x, 0.f);
                v.y = fmaxf(v.y * csc.y + csh.y, 0.f);
                v.z = fmaxf(v.z * csc.z + csh.z, 0.f);
                v.w = fmaxf(v.w * csc.w + csh.w, 0.f);
            }
            pk[i] = split_pack(v);
        }
    };

    uint4 pk[8];
    convert_tile(0, pk);

    for (int kt = 0; kt < nk; kt++) {
        if (kt) { MBARRIER_WAIT_PARITY(sb + SM_MBAR, ph); ph ^= 1; }

        if (tid == 0) {
            MBARRIER_EXPECT_TX(sb + SM_MBT, 65536u);
            bulk_cp(sb + SM_BH, Bh + (size_t)kt * 32768, 32768u, sb + SM_MBT);
            bulk_cp(sb + SM_BL, Bl + (size_t)kt * 32768, 32768u, sb + SM_MBT);
        }
        #pragma unroll
        for (int i = 0; i < 8; i++) {
            *(uint2*)(smem + SM_AH + so[i]) = make_uint2(pk[i].x, pk[i].y);
            *(uint2*)(smem + SM_AL + so[i]) = make_uint2(pk[i].z, pk[i].w);
        }
        FENCE_ASYNC_SHARED();
        __syncthreads();
        if (wid == 0) {
            MBARRIER_WAIT_PARITY(sb + SM_MBT, ph_t);
            if (elect_one_pred()) {
                #pragma unroll
                for (int sp = 0; sp < 3; sp++) {
                    uint64_t ad = (sp == 2) ? aL : aH;
                    uint64_t bd = (sp == 1) ? bL : bH;
                    #pragma unroll
                    for (int c = 0; c < 4; c++) {
                        uint32_t en = (kt == 0 && sp == 0 && c == 0) ? 0u : 1u;
                        mma_f16_ss(tmem, ad + c * 2, bd + c * 2, IDESC_G, en);
                    }
                }
                TCGEN05_COMMIT(sb + SM_MBAR);
            }
        }
        ph_t ^= 1;
        if (kt + 1 < nk) convert_tile(kt + 1, pk);
    }
    MBARRIER_WAIT_PARITY(sb + SM_MBAR, ph);
    TCGEN05_FENCE_AFTER();

    if (wid < 4) {
        int row = m0 + wid * 32 + lane;
        float s_acc = 0.f, d_acc = 0.f;
        #pragma unroll
        for (int j = 0; j < 8; j++) {
            uint32_t r[32];
            TCGEN05_LD_X32(r, tmem + j * 32);
            TCGEN05_WAIT_LD();
            #pragma unroll
            for (int q = 0; q < 32; q++) {
                float f = __uint_as_float(r[q]);
                s_acc += f * sAS[j * 32 + q];
                d_acc += f * sAD[j * 32 + q];
            }
            if (row < M) {
                float4* dst = (float4*)(C + (size_t)row * D_HID + j * 32);
                #pragma unroll
                for (int q = 0; q < 8; q++)
                    dst[q] = make_float4(__uint_as_float(r[q * 4 + 0]), __uint_as_float(r[q * 4 + 1]),
                                         __uint_as_float(r[q * 4 + 2]), __uint_as_float(r[q * 4 + 3]));
            }
        }
        if (row < M) { as_out[row] = s_acc; ad_out[row] = d_acc; }
        TCGEN05_FENCE_BEFORE();
    }
    __syncthreads();
    if (tid == 0) {
        asm volatile("mbarrier.inval.shared.b64 [%0];" :: "r"(sb + SM_MBAR) : "memory");
        asm volatile("mbarrier.inval.shared.b64 [%0];" :: "r"(sb + SM_MBT) : "memory");
    }
    __syncthreads();
    if (wid == 0) TCGEN05_DEALLOC(tmem, 256);
#else
    // Correct scalar fallback for the non-arch-specific PTX pass.
    int tid = threadIdx.x;
    if (tid >= 128) return;
    int gr = blockIdx.x * 128 + tid;
    if (gr >= M) return;
    float rs = rowscale ? rowscale[gr] : 1.0f;
    float s_acc = 0.f, d_acc = 0.f;
    for (int n = 0; n < 256; n++) {
        float acc = 0.f;
        for (int k = 0; k < K; k++) {
            int kt = k >> 6, kk = k & 63;
            uint32_t off = (uint32_t)(n * 128 + kk * 2);
            off ^= ((off >> 3) & 0x70);
            float w = __bfloat162float(*(const __nv_bfloat16*)(Bh + (size_t)kt * 32768 + off))
                    + __bfloat162float(*(const __nv_bfloat16*)(Bl + (size_t)kt * 32768 + off));
            float a = A[(size_t)gr * K + k] * rs;
            if (colsc) a = fmaxf(a * colsc[k] + colsh[k], 0.f);
            acc += a * w;
        }
        C[(size_t)gr * 256 + n] = acc;
        s_acc += acc * a_s[n];
        d_acc += acc * a_d[n];
    }
    as_out[gr] = s_acc; ad_out[gr] = d_acc;
#endif
}

// ---------------- zero/init (single launch) ----------------
__global__ void k_zero_all(float* bnsum, float* bnsq, float* pool, int* cnt, int* dcnt) {
    int i = blockIdx.x * blockDim.x + threadIdx.x;
    if (i < N_NODES) dcnt[i] = 0;
    if (i < N_GRAPHS * D_HID) pool[i] = 0.0f;
    if (i < D_HID) { bnsum[i] = 0.0f; bnsq[i] = 0.0f; }
    if (i < N_GRAPHS) cnt[i] = 0;
}

// ---------------- CSR scan ----------------
__global__ __launch_bounds__(1024) void k_scan(const int* __restrict__ dcnt,
                                               int* __restrict__ rowoff,
                                               int* __restrict__ wr) {
    __shared__ int wsum[32];
    int t = threadIdx.x;
    int lane = t & 31, w = t >> 5;
    const int CH = (N_NODES + 1023) / 1024;   // 49
    int lo = t * CH, hi = min(lo + CH, N_NODES);
    int s = 0;
    for (int i = lo; i < hi; i++) s += dcnt[i];
    int inc = s;
    #pragma unroll
    for (int o = 1; o < 32; o <<= 1) {
        int v = __shfl_up_sync(0xffffffffu, inc, o);
        if (lane >= o) inc += v;
    }
    if (lane == 31) wsum[w] = inc;
    __syncthreads();
    if (w == 0) {
        int v = (lane < 32) ? wsum[lane] : 0;
        int wi = v;
        #pragma unroll
        for (int o = 1; o < 32; o <<= 1) {
            int u = __shfl_up_sync(0xffffffffu, wi, o);
            if (lane >= o) wi += u;
        }
        wsum[lane] = wi - v;   // exclusive
        if (lane == 31) rowoff[N_NODES] = wi;
    }
    __syncthreads();
    int run = wsum[w] + inc - s;
    for (int i = lo; i < hi; i++) {
        rowoff[i] = run; wr[i] = run;
        run += dcnt[i];
    }
}

// ---- score helper: attn numerator for edge (s -> d), no max-shift ----
__device__ __forceinline__ float edge_ex(const float* __restrict__ as, float add, int s) {
    float e = __ldg(as + s) + add;
    e = (e > 0.f) ? e : NEG_SLOPE * e;
    return __expf(e);
}

// Dual-destination CSR gather: warp handles d0 and d1; interleaved edge
// chains give MLP=2 without shfl overhead.
__device__ __forceinline__ void gather_pair(
    const float* __restrict__ h,
    const int* __restrict__ rowoff, const int* __restrict__ srcid,
    const float* __restrict__ as, const float* __restrict__ ad,
    int d0, int d1, int lane,
    float4& x0, float4& x1, float4& y0, float4& y1)
{
    int beg0 = rowoff[d0], end0 = rowoff[d0 + 1];
    int beg1, end1;
    if (d1 < N_NODES) { beg1 = rowoff[d1]; end1 = rowoff[d1 + 1]; }
    else { beg1 = 0; end1 = 0; }
    float add0 = ad[d0];
    float add1 = (d1 < N_NODES) ? ad[d1] : 0.f;
    float p0 = 0.f, p1 = 0.f;
    for (int i = beg0 + lane; i < end0; i += 32) p0 += edge_ex(as, add0, srcid[i]);
    for (int i = beg1 + lane; i < end1; i += 32) p1 += edge_ex(as, add1, srcid[i]);
    float inv0 = __frcp_rn(warp_red(p0));
    float inv1 = __frcp_rn(warp_red(p1));

    x0 = make_float4(0.f, 0.f, 0.f, 0.f); x1 = x0;
    y0 = x0; y1 = x0;
    int deg0 = end0 - beg0, deg1 = end1 - beg1;
    int n = deg0 > deg1 ? deg0 : deg1;
    for (int j = 0; j < n; j++) {
        bool q0 = j < deg0, q1 = j < deg1;
        int s0 = q0 ? srcid[beg0 + j] : 0;
        int s1 = q1 ? srcid[beg1 + j] : 0;
        float at0 = q0 ? edge_ex(as, add0, s0) * inv0 : 0.f;
        float at1 = q1 ? edge_ex(as, add1, s1) * inv1 : 0.f;
        const float4* h0 = (const float4*)(h + (size_t)s0 * D_HID);
        const float4* h1 = (const float4*)(h + (size_t)s1 * D_HID);
        float4 u0 = h0[lane], u1 = h0[lane + 32];
        float4 w0 = h1[lane], w1 = h1[lane + 32];
        x0.x += at0 * u0.x; x0.y += at0 * u0.y; x0.z += at0 * u0.z; x0.w += at0 * u0.w;
        x1.x += at0 * u1.x; x1.y += at0 * u1.y; x1.z += at0 * u1.z; x1.w += at0 * u1.w;
        y0.x += at1 * w0.x; y0.y += at1 * w0.y; y0.z += at1 * w0.z; y0.w += at1 * w0.w;
        y1.x += at1 * w1.x; y1.y += at1 * w1.y; y1.z += at1 * w1.z; y1.w += at1 * w1.w;
    }
}

// ------- fused GAT edge phase (layer 1): softmax + CSR aggregation -------
__global__ void k_agg_fused(const float* __restrict__ h, float* __restrict__ agg,
                            const int* __restrict__ rowoff, const int* __restrict__ srcid,
                            const float* __restrict__ as, const float* __restrict__ ad) {
    int w = (int)(((size_t)blockIdx.x * blockDim.x + threadIdx.x) >> 5);
    int lane = threadIdx.x & 31;
    int d0 = w * 2;
    if (d0 >= N_NODES) return;
    int d1 = d0 + 1;
    float4 x0, x1, y0, y1;
    gather_pair(h, rowoff, srcid, as, ad, d0, d1, lane, x0, x1, y0, y1);
    float4* o0 = (float4*)(agg + (size_t)d0 * D_HID);
    o0[lane] = x0; o0[lane + 32] = x1;
    if (d1 < N_NODES) {
        float4* o1 = (float4*)(agg + (size_t)d1 * D_HID);
        o1[lane] = y0; o1[lane + 32] = y1;
    }
}

// ------- fused edge phase (layer 2): softmax + agg + relu(+b2) + mean-pool -------
__global__ void k_agg_pool_fused(const float* __restrict__ h,
                                 const int* __restrict__ rowoff, const int* __restrict__ srcid,
                                 const float* __restrict__ as, const float* __restrict__ ad,
                                 const float* __restrict__ b2,
                                 const int* __restrict__ batch,
                                 float* __restrict__ pool) {
    int w = (int)(((size_t)blockIdx.x * blockDim.x + threadIdx.x) >> 5);
    int lane = threadIdx.x & 31;
    int d0 = w * 2;
    if (d0 >= N_NODES) return;
    int d1 = d0 + 1;
    float4 x0, x1, y0, y1;
    gather_pair(h, rowoff, srcid, as, ad, d0, d1, lane, x0, x1, y0, y1);
    float4 b0 = ((const float4*)b2)[lane];
    float4 b1 = ((const float4*)b2)[lane + 32];
    x0.x = fmaxf(x0.x + b0.x, 0.f); x0.y = fmaxf(x0.y + b0.y, 0.f);
    x0.z = fmaxf(x0.z + b0.z, 0.f); x0.w = fmaxf(x0.w + b0.w, 0.f);
    x1.x = fmaxf(x1.x + b1.x, 0.f); x1.y = fmaxf(x1.y + b1.y, 0.f);
    x1.z = fmaxf(x1.z + b1.z, 0.f); x1.w = fmaxf(x1.w + b1.w, 0.f);
    int g0 = batch[d0];
    float4* pg0 = (float4*)(pool + (size_t)g0 * D_HID);
    asm volatile("red.global.add.v4.f32 [%0], {%1,%2,%3,%4};"
                 :: "l"(pg0 + lane), "f"(x0.x), "f"(x0.y), "f"(x0.z), "f"(x0.w) : "memory");
    asm volatile("red.global.add.v4.f32 [%0], {%1,%2,%3,%4};"
                 :: "l"(pg0 + lane + 32), "f"(x1.x), "f"(x1.y), "f"(x1.z), "f"(x1.w) : "memory");
    if (d1 < N_NODES) {
        y0.x = fmaxf(y0.x + b0.x, 0.f); y0.y = fmaxf(y0.y + b0.y, 0.f);
        y0.z = fmaxf(y0.z + b0.z, 0.f); y0.w = fmaxf(y0.w + b0.w, 0.f);
        y1.x = fmaxf(y1.x + b1.x, 0.f); y1.y = fmaxf(y1.y + b1.y, 0.f);
        y1.z = fmaxf(y1.z + b1.z, 0.f); y1.w = fmaxf(y1.w + b1.w, 0.f);
        int g1 = batch[d1];
        float4* pg1 = (float4*)(pool + (size_t)g1 * D_HID);
        asm volatile("red.global.add.v4.f32 [%0], {%1,%2,%3,%4};"
                     :: "l"(pg1 + lane), "f"(y0.x), "f"(y0.y), "f"(y0.z), "f"(y0.w) : "memory");
        asm volatile("red.global.add.v4.f32 [%0], {%1,%2,%3,%4};"
                     :: "l"(pg1 + lane + 32), "f"(y1.x), "f"(y1.y), "f"(y1.z), "f"(y1.w) : "memory");
    }
}

// ---------------- BatchNorm stats ----------------
#define ROWS_PER_BLK 64
__global__ void k_bnstats(const float* __restrict__ h, float* __restrict__ bsum,
                          float* __restrict__ bsq) {
    int col = threadIdx.x;
    int r0 = blockIdx.x * ROWS_PER_BLK;
    int r1 = min(r0 + ROWS_PER_BLK, N_NODES);
    float s = 0.f, q = 0.f;
    for (int r = r0; r < r1; r++) {
        float v = h[(size_t)r * D_HID + col];
        s += v; q += v * v;
    }
    atomicAdd(&bsum[col], s);
    atomicAdd(&bsq[col], q);
}

// ---------------- BN finalize: per-column scale/shift ----------------
__global__ void k_bnfin(const float* __restrict__ bsum, const float* __restrict__ bsq,
                        const float* __restrict__ gamma, const float* __restrict__ beta,
                        float* __restrict__ sc, float* __restrict__ sh) {
    int col = threadIdx.x;
    float mu = bsum[col] * (1.0f / N_NODES);
    float var = bsq[col] * (1.0f / N_NODES) - mu * mu;
    float s = gamma[col] * rsqrtf(var + EPS_BN);
    sc[col] = s;
    sh[col] = beta[col] - mu * s;
}

// ---------------- classifier ----------------
__global__ void k_clf(const float* __restrict__ pool, const int* __restrict__ cnt,
                      const float* __restrict__ claim, const float* __restrict__ W,
                      const float* __restrict__ bias, float* __restrict__ out) {
    __shared__ float red[256];
    int b = blockIdx.x;
    int t = threadIdx.x;
    float c = fmaxf((float)cnt[b], 1.0f);
    float part = (pool[b * D_HID + t] / c) * W[t];
    #pragma unroll
    for (int j = 0; j < 3; j++) {
        int k = t + j * 256;
        part += claim[(size_t)b * D_IN + k] * W[D_HID + k];
    }
    red[t] = part;
    __syncthreads();
    #pragma unroll
    for (int o = 128; o; o >>= 1) {
        if (t < o) red[t] += red[t + o];
        __syncthreads();
    }
    if (t == 0) out[b] = red[0] + bias[0];
}

// ---------------- host launcher ----------------
extern "C" void kernel_launch(void* const* d_in, const int* in_sizes, int n_in,
                              void* d_out, int out_size) {
    const float* claim   = (const float*)d_in[0];
    const float* x       = (const float*)d_in[1];
    const int*   ei      = (const int*)d_in[2];
    const int*   batch   = (const int*)d_in[3];
    const float* W1      = (const float*)d_in[4];
    const float* a_src1  = (const float*)d_in[5];
    const float* a_dst1  = (const float*)d_in[6];
    // d_in[7] = b1 : provably no-op through training-mode BatchNorm
    const float* W2      = (const float*)d_in[8];
    const float* a_src2  = (const float*)d_in[9];
    const float* a_dst2  = (const float*)d_in[10];
    const float* b2      = (const float*)d_in[11];
    const float* gamma   = (const float*)d_in[12];
    const float* beta    = (const float*)d_in[13];
    const float* clfW    = (const float*)d_in[14];
    const float* clfb    = (const float*)d_in[15];
    float* out = (float*)d_out;

    float *p_rel, *p_A, *p_B, *p_as, *p_ad, *p_bnsum, *p_bnsq, *p_bnsc, *p_bnsh, *p_pool;
    int *p_cnt, *p_dcnt, *p_rowoff, *p_wr, *p_srcid;
    unsigned char *p_w1h, *p_w1l, *p_w2h, *p_w2l;
    cudaGetSymbolAddress((void**)&p_rel, g_rel);
    cudaGetSymbolAddress((void**)&p_A, g_bufA);
    cudaGetSymbolAddress((void**)&p_B, g_bufB);
    cudaGetSymbolAddress((void**)&p_as, g_as);
    cudaGetSymbolAddress((void**)&p_ad, g_ad);
    cudaGetSymbolAddress((void**)&p_bnsum, g_bnsum);
    cudaGetSymbolAddress((void**)&p_bnsq, g_bnsq);
    cudaGetSymbolAddress((void**)&p_bnsc, g_bnsc);
    cudaGetSymbolAddress((void**)&p_bnsh, g_bnsh);
    cudaGetSymbolAddress((void**)&p_pool, g_pool);
    cudaGetSymbolAddress((void**)&p_cnt, g_cnt);
    cudaGetSymbolAddress((void**)&p_dcnt, g_dcnt);
    cudaGetSymbolAddress((void**)&p_rowoff, g_rowoff);
    cudaGetSymbolAddress((void**)&p_wr, g_wr);
    cudaGetSymbolAddress((void**)&p_srcid, g_srcid);
    cudaGetSymbolAddress((void**)&p_w1h, g_w1h);
    cudaGetSymbolAddress((void**)&p_w1l, g_w1l);
    cudaGetSymbolAddress((void**)&p_w2h, g_w2h);
    cudaGetSymbolAddress((void**)&p_w2l, g_w2l);

    cudaFuncSetAttribute(k_gemm_tc, cudaFuncAttributeMaxDynamicSharedMemorySize, SM_SZ);

    const int chunkBlocks = (N_NODES + ROWS_PER_BLK - 1) / ROWS_PER_BLK;
    const int gemmBlocks = (N_NODES + 127) / 128;

    // launch order: GEMM1 stays the 4th launch (ncu captures #4).
    k_zero_all<<<NODE_BLKS, 256>>>(p_bnsum, p_bnsq, p_pool, p_cnt, p_dcnt);
    k_misc1<<<WNODE_BLKS + EDGE_BLKS + PREP1_BLKS, 256>>>(
        claim, x, batch, p_rel, p_cnt, ei, p_dcnt, W1, p_w1h, p_w1l);
    k_scan<<<1, 1024>>>(p_dcnt, p_rowoff, p_wr);
    k_gemm_tc<<<gemmBlocks, 256, SM_SZ>>>(x, D_IN, p_w1h, p_w1l, p_A,
                                          p_rel, nullptr, nullptr,
                                          a_src1, a_dst1, p_as, p_ad, N_NODES);
    k_misc2<<<EDGE_BLKS + PREP2_BLKS, 256>>>(ei, p_wr, p_srcid, W2, p_w2h, p_w2l);

    // ---- layer 1: fused softmax + aggregation (dual-dst warps) ----
    k_agg_fused<<<WPAIR_BLKS, 256>>>(p_A, p_B, p_rowoff, p_srcid, p_as, p_ad);

    // ---- BN stats + finalize (apply fused into GEMM2's A-loader) ----
    k_bnstats<<<chunkBlocks, 256>>>(p_B, p_bnsum, p_bnsq);
    k_bnfin<<<1, 256>>>(p_bnsum, p_bnsq, gamma, beta, p_bnsc, p_bnsh);

    // ---- layer 2: GEMM (BN+ReLU fused) + fused edge phase + pooling ----
    k_gemm_tc<<<gemmBlocks, 256, SM_SZ>>>(p_B, D_HID, p_w2h, p_w2l, p_A,
                                          nullptr, p_bnsc, p_bnsh,
                                          a_src2, a_dst2, p_as, p_ad, N_NODES);
    k_agg_pool_fused<<<WPAIR_BLKS, 256>>>(p_A, p_rowoff, p_srcid, p_as, p_ad,
                                          b2, batch, p_pool);

    // ---- classifier ----
    k_clf<<<N_GRAPHS, 256>>>(p_pool, p_cnt, claim, clfW, clfb, out);
}

// round 15
// speedup vs baseline: 1.0654x; 1.0653x over previous
#include <cuda_runtime.h>
#include <cuda_bf16.h>
#include <cstdint>

#define N_NODES   50000
#define N_EDGES   400000
#define E_TOT     (N_EDGES + N_NODES)
#define N_GRAPHS  128
#define D_IN      768
#define D_HID     256
#define NEG_SLOPE 0.2f
#define EPS_COS   1e-8f
#define EPS_BN    1e-5f

#if defined(__CUDA_ARCH_FEAT_SM103_ALL) || defined(__CUDA_ARCH_SPECIFIC__)
#define HAS_TCGEN05 1
#else
#define HAS_TCGEN05 0
#endif

// ---------------- scratch (device globals; no allocation) ----------------
__device__ float    g_rel[N_NODES];
__device__ float    g_bufA[(size_t)N_NODES * D_HID];
__device__ float    g_bufB[(size_t)N_NODES * D_HID];
__device__ float    g_as[N_NODES];
__device__ float    g_ad[N_NODES];
__device__ float    g_bnsum[D_HID];
__device__ float    g_bnsq[D_HID];
__device__ float    g_pool[N_GRAPHS * D_HID];
__device__ int      g_cnt[N_GRAPHS];
// CSR (built once, reused by both layers)
__device__ int      g_dcnt[N_NODES];
__device__ int      g_rowoff[N_NODES + 1];
__device__ int      g_wr[N_NODES];
__device__ int      g_srcid[E_TOT];
// pre-swizzled bf16 hi/lo weight images: [ktile64][256 n-rows][128 bytes] SW128
__device__ unsigned char g_w1h[12 * 32768];
__device__ unsigned char g_w1l[12 * 32768];
__device__ unsigned char g_w2h[4 * 32768];
__device__ unsigned char g_w2l[4 * 32768];

// ---------------- PTX helpers ----------------
__device__ __forceinline__ uint32_t elect_one_pred() {
    uint32_t pred;
    asm volatile(
        "{\n\t.reg .pred p;\n\t"
        "elect.sync _|p, 0xFFFFFFFF;\n\t"
        "selp.b32 %0, 1, 0, p;\n\t}"
        : "=r"(pred));
    return pred;
}
__device__ __forceinline__ uint32_t smem_to_u32(const void* p) {
    uint32_t a;
    asm("{ .reg .u64 t; cvta.to.shared.u64 t, %1; cvt.u32.u64 %0, t; }"
        : "=r"(a) : "l"(p));
    return a;
}
#define MBARRIER_INIT(addr, cnt) \
    asm volatile("mbarrier.init.shared.b64 [%0], %1;" :: "r"((uint32_t)(addr)), "r"((uint32_t)(cnt)) : "memory")
#define MBARRIER_EXPECT_TX(addr, bytes) \
    asm volatile("mbarrier.arrive.expect_tx.shared.b64 _, [%0], %1;" \
        :: "r"((uint32_t)(addr)), "r"((uint32_t)(bytes)) : "memory")
#define MBARRIER_WAIT_PARITY(addr, parity) do { \
    uint32_t _m = (uint32_t)(addr); uint32_t _p = (uint32_t)(parity); uint32_t _d; \
    asm volatile("{\n\t.reg .pred p;\n\t" \
        "mbarrier.try_wait.parity.acquire.cta.shared::cta.b64 p, [%1], %2;\n\t" \
        "selp.b32 %0, 1, 0, p;\n\t}" : "=r"(_d) : "r"(_m), "r"(_p) : "memory"); \
    if (!_d) { \
        asm volatile("{\n\t.reg .pred P1;\n\t" \
            "WL_%=:\n\t" \
            "mbarrier.try_wait.parity.acquire.cta.shared::cta.b64 P1, [%0], %1, 0x989680;\n\t" \
            "@P1 bra.uni WD_%=;\n\t" \
            "bra.uni WL_%=;\n\t" \
            "WD_%=:\n\t}" :: "r"(_m), "r"(_p) : "memory"); \
    } \
} while (0)
#define TCGEN05_ALLOC(sa, n) \
    asm volatile("tcgen05.alloc.cta_group::1.sync.aligned.shared::cta.b32 [%0], %1;" \
        :: "r"((uint32_t)(sa)), "r"((uint32_t)(n)) : "memory")
#define TCGEN05_DEALLOC(t, n) \
    asm volatile("tcgen05.dealloc.cta_group::1.sync.aligned.b32 %0, %1;" :: "r"(t), "r"((uint32_t)(n)))
#define TCGEN05_RELINQ() \
    asm volatile("tcgen05.relinquish_alloc_permit.cta_group::1.sync.aligned;")
#define TCGEN05_COMMIT(mb) \
    asm volatile("tcgen05.commit.cta_group::1.mbarrier::arrive::one.shared::cluster.b64 [%0];" \
        :: "r"((uint32_t)(mb)) : "memory")
#define TCGEN05_FENCE_AFTER()  asm volatile("tcgen05.fence::after_thread_sync;" ::: "memory")
#define TCGEN05_FENCE_BEFORE() asm volatile("tcgen05.fence::before_thread_sync;" ::: "memory")
#define TCGEN05_WAIT_LD()      asm volatile("tcgen05.wait::ld.sync.aligned;" ::: "memory")
#define FENCE_ASYNC_SHARED()   asm volatile("fence.proxy.async.shared::cta;" ::: "memory")
#define TCGEN05_LD_X32(r, ta) \
    asm volatile("tcgen05.ld.sync.aligned.32x32b.x32.b32 " \
        "{%0, %1, %2, %3, %4, %5, %6, %7, %8, %9, %10, %11, %12, %13, %14, %15, " \
        " %16, %17, %18, %19, %20, %21, %22, %23, %24, %25, %26, %27, %28, %29, %30, %31}, [%32];" \
        : "=r"((r)[0]), "=r"((r)[1]), "=r"((r)[2]), "=r"((r)[3]), \
          "=r"((r)[4]), "=r"((r)[5]), "=r"((r)[6]), "=r"((r)[7]), \
          "=r"((r)[8]), "=r"((r)[9]), "=r"((r)[10]), "=r"((r)[11]), \
          "=r"((r)[12]), "=r"((r)[13]), "=r"((r)[14]), "=r"((r)[15]), \
          "=r"((r)[16]), "=r"((r)[17]), "=r"((r)[18]), "=r"((r)[19]), \
          "=r"((r)[20]), "=r"((r)[21]), "=r"((r)[22]), "=r"((r)[23]), \
          "=r"((r)[24]), "=r"((r)[25]), "=r"((r)[26]), "=r"((r)[27]), \
          "=r"((r)[28]), "=r"((r)[29]), "=r"((r)[30]), "=r"((r)[31]) \
        : "r"(ta))

static constexpr uint64_t SMEM_DESC_BASE_SW128 =
    (uint64_t(2) << 61) | (uint64_t(1) << 46) | (uint64_t(64) << 32) | (uint64_t(1) << 16);
__device__ __forceinline__ uint64_t make_desc(uint32_t addr) {
    return SMEM_DESC_BASE_SW128 | ((uint64_t)(addr >> 4) & 0x3FFF);
}
// idesc: dtype=F32, atype=btype=BF16, N=256, M=128
#define IDESC_G 0x8400490u

#if HAS_TCGEN05
__device__ __forceinline__ void mma_f16_ss(uint32_t d, uint64_t ad, uint64_t bd,
                                           uint32_t idesc, uint32_t en) {
    asm volatile(
        "{\n\t.reg .pred p;\n\t"
        "setp.ne.u32 p, %5, 0;\n\t"
        "tcgen05.mma.cta_group::1.kind::f16 [%0], %1, %2, %3, {%4, %4, %4, %4}, p;\n\t}"
        :: "r"(d), "l"(ad), "l"(bd), "r"(idesc), "r"(0u), "r"(en) : "memory");
}
__device__ __forceinline__ void bulk_cp(uint32_t dst, const void* src, uint32_t bytes,
                                        uint32_t mb) {
    asm volatile(
        "cp.async.bulk.shared::cta.global.mbarrier::complete_tx::bytes [%0], [%1], %2, [%3];"
        :: "r"(dst), "l"(src), "r"(bytes), "r"(mb) : "memory");
}
#endif

__device__ __forceinline__ float warp_red(float v) {
    #pragma unroll
    for (int o = 16; o; o >>= 1) v += __shfl_xor_sync(0xffffffffu, v, o);
    return v;
}
// packed pair convert: res = bf16(a) | bf16(b)<<16
#define CVT2(res, a_, b_) \
    asm("cvt.rn.bf16x2.f32 %0, %1, %2;" : "=r"(res) : "f"(b_), "f"(a_))

// convert float4 -> packed {hi01, hi23, lo01, lo23}
__device__ __forceinline__ uint4 split_pack(float4 v) {
    uint4 pk;
    CVT2(pk.x, v.x, v.y);
    CVT2(pk.y, v.z, v.w);
    float h0 = __uint_as_float(pk.x << 16);
    float h1 = __uint_as_float(pk.x & 0xFFFF0000u);
    float h2 = __uint_as_float(pk.y << 16);
    float h3 = __uint_as_float(pk.y & 0xFFFF0000u);
    CVT2(pk.z, v.x - h0, v.y - h1);
    CVT2(pk.w, v.z - h2, v.w - h3);
    return pk;
}

// ---------------- kernel bodies (device functions for fusion) ----------------
__device__ void body_prep_w(int blk, const float* __restrict__ W, int K,
                            unsigned char* __restrict__ hi, unsigned char* __restrict__ lo) {
    int idx = blk * 256 + threadIdx.x;
    if (idx >= K * 256) return;
    int k = idx >> 8, n = idx & 255;
    float v = W[idx];
    __nv_bfloat16 h = __float2bfloat16_rn(v);
    __nv_bfloat16 l = __float2bfloat16_rn(v - __bfloat162float(h));
    int kt = k >> 6, kk = k & 63;
    uint32_t off = (uint32_t)(n * 128 + kk * 2);
    off ^= ((off >> 3) & 0x70);
    size_t base = (size_t)kt * 32768 + off;
    *(__nv_bfloat16*)(hi + base) = h;
    *(__nv_bfloat16*)(lo + base) = l;
}

__device__ void body_rel(int blk, const float* __restrict__ claim, const float* __restrict__ x,
                         const int* __restrict__ batch, float* __restrict__ rel,
                         int* __restrict__ cnt) {
    int warp = (blk * 256 + threadIdx.x) >> 5;
    int lane = threadIdx.x & 31;
    if (warp >= N_NODES) return;
    int b = batch[warp];
    const float4* ce = (const float4*)(claim + (size_t)b * D_IN);
    const float4* xv = (const float4*)(x + (size_t)warp * D_IN);
    float dot = 0.f, nc = 0.f, nx = 0.f;
    #pragma unroll
    for (int k = lane; k < D_IN / 4; k += 32) {
        float4 c = ce[k], v = xv[k];
        dot += c.x * v.x + c.y * v.y + c.z * v.z + c.w * v.w;
        nc  += c.x * c.x + c.y * c.y + c.z * c.z + c.w * c.w;
        nx  += v.x * v.x + v.y * v.y + v.z * v.z + v.w * v.w;
    }
    dot = warp_red(dot); nc = warp_red(nc); nx = warp_red(nx);
    if (lane == 0) {
        float nrm = sqrtf(nc) * sqrtf(nx);
        rel[warp] = dot / fmaxf(nrm, EPS_COS);
        atomicAdd(&cnt[b], 1);
    }
}

__device__ void body_hist(int blk, const int* __restrict__ ei, int* __restrict__ dcnt) {
    int i = blk * 256 + threadIdx.x;
    if (i >= E_TOT) return;
    int d = (i < N_EDGES) ? ei[N_EDGES + i] : (i - N_EDGES);
    atomicAdd(&dcnt[d], 1);
}

__device__ void body_fill(int blk, const int* __restrict__ ei, int* __restrict__ wr,
                          int* __restrict__ srcid) {
    int i = blk * 256 + threadIdx.x;
    if (i >= E_TOT) return;
    int s, d;
    if (i < N_EDGES) { s = ei[i]; d = ei[N_EDGES + i]; }
    else { s = d = i - N_EDGES; }
    int pos = atomicAdd(&wr[d], 1);
    srcid[pos] = s;
}

// ---- fused independent kernels (block-range dispatch) ----
#define NODE_BLKS  ((N_NODES + 255) / 256)
#define EDGE_BLKS  ((E_TOT + 255) / 256)
#define WNODE_BLKS ((N_NODES * 32 + 255) / 256)
#define PREP1_BLKS ((D_IN * 256 + 255) / 256)
#define PREP2_BLKS ((D_HID * 256 + 255) / 256)

__global__ void k_misc1(const float* claim, const float* x, const int* batch,
                        float* rel, int* cnt, const int* ei, int* dcnt,
                        const float* W1, unsigned char* w1h, unsigned char* w1l) {
    int b = blockIdx.x;
    if (b < WNODE_BLKS) { body_rel(b, claim, x, batch, rel, cnt); return; }
    b -= WNODE_BLKS;
    if (b < EDGE_BLKS) { body_hist(b, ei, dcnt); return; }
    b -= EDGE_BLKS;
    body_prep_w(b, W1, D_IN, w1h, w1l);
}
__global__ void k_misc2(const int* ei, int* wr, int* srcid,
                        const float* W2, unsigned char* w2h, unsigned char* w2l) {
    int b = blockIdx.x;
    if (b < EDGE_BLKS) { body_fill(b, ei, wr, srcid); return; }
    b -= EDGE_BLKS;
    body_prep_w(b, W2, D_HID, w2h, w2l);
}

// -------- tcgen05 GEMM (K=64 single stage, 256 thr, occ=2, cvt-in-shadow) ----
// BN apply is fused: when bnsum != nullptr the loader computes per-column
// scale/shift from bnsum/bnsq/gamma/beta once (hoisted) and applies
// relu(v*sc+sh) to A.
#define SM_TPTR 0
#define SM_MBAR 8
#define SM_MBT  16
#define SM_ASV  1024
#define SM_ADV  2048
#define SM_AH   3072
#define SM_AL   (SM_AH + 16384)
#define SM_BH   (SM_AL + 16384)
#define SM_BL   (SM_BH + 32768)
#define SM_SZ   (SM_BL + 32768)

__global__ __launch_bounds__(256, 2) void k_gemm_tc(
    const float* __restrict__ A, int K,
    const unsigned char* __restrict__ Bh, const unsigned char* __restrict__ Bl,
    float* __restrict__ C,
    const float* __restrict__ rowscale,
    const float* __restrict__ bnsum, const float* __restrict__ bnsq,
    const float* __restrict__ gamma, const float* __restrict__ beta,
    const float* __restrict__ a_s, const float* __restrict__ a_d,
    float* __restrict__ as_out, float* __restrict__ ad_out, int M)
{
#if HAS_TCGEN05
    extern __shared__ char smem[];
    uint32_t sb = smem_to_u32(smem);
    int tid = threadIdx.x, wid = tid >> 5, lane = tid & 31;
    int m0 = blockIdx.x * 128;

    if (tid == 0) { MBARRIER_INIT(sb + SM_MBAR, 1); MBARRIER_INIT(sb + SM_MBT, 1); }
    if (wid == 0) TCGEN05_ALLOC(sb + SM_TPTR, 256);
    float* sAS = (float*)(smem + SM_ASV);
    float* sAD = (float*)(smem + SM_ADV);
    if (tid < 256) { sAS[tid] = a_s[tid]; sAD[tid] = a_d[tid]; }
    __syncthreads();
    uint32_t tmem;
    asm volatile("ld.shared.b32 %0, [%1];" : "=r"(tmem) : "r"(sb + SM_TPTR));
    if (wid == 0) TCGEN05_RELINQ();

    const uint64_t aH = make_desc(sb + SM_AH);
    const uint64_t aL = make_desc(sb + SM_AL);
    const uint64_t bH = make_desc(sb + SM_BH);
    const uint64_t bL = make_desc(sb + SM_BL);

    int rbase = tid >> 4;        // 0..15
    int cq = (tid & 15) << 2;    // 0,4,...,60
    int ph = 0, ph_t = 0;
    const int nk = K >> 6;
    const bool has_bn = (bnsum != nullptr);

    float s_row[8];
    #pragma unroll
    for (int i = 0; i < 8; i++) {
        int gr = m0 + i * 16 + rbase;
        s_row[i] = (rowscale && gr < M) ? rowscale[gr] : 1.0f;
    }
    uint32_t so[8];
    #pragma unroll
    for (int i = 0; i < 8; i++) {
        uint32_t off = (uint32_t)((i * 16 + rbase) * 128 + cq * 2);
        so[i] = off ^ ((off >> 3) & 0x70);
    }

    // hoisted per-column BN params for each K-tile this thread touches
    // (columns k0+cq..k0+cq+3 per tile; K<=256 for the BN layer => nk<=4)
    float4 csc_t[4], csh_t[4];
    if (has_bn) {
        #pragma unroll
        for (int t = 0; t < 4; t++) {
            if (t < nk) {
                int c0 = (t << 6) + cq;
                float4 su = *(const float4*)(bnsum + c0);
                float4 sq = *(const float4*)(bnsq + c0);
                float4 ga = *(const float4*)(gamma + c0);
                float4 be = *(const float4*)(beta + c0);
                float4 sc, sh;
                float mu, var;
                mu = su.x * (1.0f / N_NODES); var = sq.x * (1.0f / N_NODES) - mu * mu;
                sc.x = ga.x * rsqrtf(var + EPS_BN); sh.x = be.x - mu * sc.x;
                mu = su.y * (1.0f / N_NODES); var = sq.y * (1.0f / N_NODES) - mu * mu;
                sc.y = ga.y * rsqrtf(var + EPS_BN); sh.y = be.y - mu * sc.y;
                mu = su.z * (1.0f / N_NODES); var = sq.z * (1.0f / N_NODES) - mu * mu;
                sc.z = ga.z * rsqrtf(var + EPS_BN); sh.z = be.z - mu * sc.z;
                mu = su.w * (1.0f / N_NODES); var = sq.w * (1.0f / N_NODES) - mu * mu;
                sc.w = ga.w * rsqrtf(var + EPS_BN); sh.w = be.w - mu * sc.w;
                csc_t[t] = sc; csh_t[t] = sh;
            }
        }
    }

    auto convert_tile = [&](int kt, uint4* pk) {
        int k0 = kt << 6;
        float4 va[8];
        #pragma unroll
        for (int i = 0; i < 8; i++) {
            int gr = m0 + i * 16 + rbase;
            va[i] = (gr < M) ? *(const float4*)(A + (size_t)gr * K + k0 + cq)
                             : make_float4(0.f, 0.f, 0.f, 0.f);
        }
        #pragma unroll
        for (int i = 0; i < 8; i++) {
            float4 v = va[i];
            float sc = s_row[i];
            v.x *= sc; v.y *= sc; v.z *= sc; v.w *= sc;
            if (has_bn) {
                float4 csc = csc_t[kt & 3], csh = csh_t[kt & 3];
                v.x = fmaxf(v.x * csc.x + csh.x, 0.f);
                v.y = fmaxf(v.y * csc.y + csh.y, 0.f);
                v.z = fmaxf(v.z * csc.z + csh.z, 0.f);
                v.w = fmaxf(v.w * csc.w + csh.w, 0.f);
            }
            pk[i] = split_pack(v);
        }
    };

    uint4 pk[8];
    convert_tile(0, pk);

    for (int kt = 0; kt < nk; kt++) {
        if (kt) { MBARRIER_WAIT_PARITY(sb + SM_MBAR, ph); ph ^= 1; }

        if (tid == 0) {
            MBARRIER_EXPECT_TX(sb + SM_MBT, 65536u);
            bulk_cp(sb + SM_BH, Bh + (size_t)kt * 32768, 32768u, sb + SM_MBT);
            bulk_cp(sb + SM_BL, Bl + (size_t)kt * 32768, 32768u, sb + SM_MBT);
        }
        #pragma unroll
        for (int i = 0; i < 8; i++) {
            *(uint2*)(smem + SM_AH + so[i]) = make_uint2(pk[i].x, pk[i].y);
            *(uint2*)(smem + SM_AL + so[i]) = make_uint2(pk[i].z, pk[i].w);
        }
        FENCE_ASYNC_SHARED();
        __syncthreads();
        if (wid == 0) {
            MBARRIER_WAIT_PARITY(sb + SM_MBT, ph_t);
            if (elect_one_pred()) {
                #pragma unroll
                for (int sp = 0; sp < 3; sp++) {
                    uint64_t ad = (sp == 2) ? aL : aH;
                    uint64_t bd = (sp == 1) ? bL : bH;
                    #pragma unroll
                    for (int c = 0; c < 4; c++) {
                        uint32_t en = (kt == 0 && sp == 0 && c == 0) ? 0u : 1u;
                        mma_f16_ss(tmem, ad + c * 2, bd + c * 2, IDESC_G, en);
                    }
                }
                TCGEN05_COMMIT(sb + SM_MBAR);
            }
        }
        ph_t ^= 1;
        if (kt + 1 < nk) convert_tile(kt + 1, pk);
    }
    MBARRIER_WAIT_PARITY(sb + SM_MBAR, ph);
    TCGEN05_FENCE_AFTER();

    if (wid < 4) {
        int row = m0 + wid * 32 + lane;
        float s_acc = 0.f, d_acc = 0.f;
        #pragma unroll
        for (int j = 0; j < 8; j++) {
            uint32_t r[32];
            TCGEN05_LD_X32(r, tmem + j * 32);
            TCGEN05_WAIT_LD();
            #pragma unroll
            for (int q = 0; q < 32; q++) {
                float f = __uint_as_float(r[q]);
                s_acc += f * sAS[j * 32 + q];
                d_acc += f * sAD[j * 32 + q];
            }
            if (row < M) {
                float4* dst = (float4*)(C + (size_t)row * D_HID + j * 32);
                #pragma unroll
                for (int q = 0; q < 8; q++)
                    dst[q] = make_float4(__uint_as_float(r[q * 4 + 0]), __uint_as_float(r[q * 4 + 1]),
                                         __uint_as_float(r[q * 4 + 2]), __uint_as_float(r[q * 4 + 3]));
            }
        }
        if (row < M) { as_out[row] = s_acc; ad_out[row] = d_acc; }
        TCGEN05_FENCE_BEFORE();
    }
    __syncthreads();
    if (tid == 0) {
        asm volatile("mbarrier.inval.shared.b64 [%0];" :: "r"(sb + SM_MBAR) : "memory");
        asm volatile("mbarrier.inval.shared.b64 [%0];" :: "r"(sb + SM_MBT) : "memory");
    }
    __syncthreads();
    if (wid == 0) TCGEN05_DEALLOC(tmem, 256);
#else
    // Correct scalar fallback for the non-arch-specific PTX pass.
    int tid = threadIdx.x;
    if (tid >= 128) return;
    int gr = blockIdx.x * 128 + tid;
    if (gr >= M) return;
    float rs = rowscale ? rowscale[gr] : 1.0f;
    float s_acc = 0.f, d_acc = 0.f;
    for (int n = 0; n < 256; n++) {
        float acc = 0.f;
        for (int k = 0; k < K; k++) {
            int kt = k >> 6, kk = k & 63;
            uint32_t off = (uint32_t)(n * 128 + kk * 2);
            off ^= ((off >> 3) & 0x70);
            float w = __bfloat162float(*(const __nv_bfloat16*)(Bh + (size_t)kt * 32768 + off))
                    + __bfloat162float(*(const __nv_bfloat16*)(Bl + (size_t)kt * 32768 + off));
            float a = A[(size_t)gr * K + k] * rs;
            if (bnsum) {
                float mu = bnsum[k] * (1.0f / N_NODES);
                float var = bnsq[k] * (1.0f / N_NODES) - mu * mu;
                float sc = gamma[k] * rsqrtf(var + EPS_BN);
                a = fmaxf(a * sc + (beta[k] - mu * sc), 0.f);
            }
            acc += a * w;
        }
        C[(size_t)gr * 256 + n] = acc;
        s_acc += acc * a_s[n];
        d_acc += acc * a_d[n];
    }
    as_out[gr] = s_acc; ad_out[gr] = d_acc;
#endif
}

// ---------------- zero/init (single launch) ----------------
__global__ void k_zero_all(float* bnsum, float* bnsq, float* pool, int* cnt, int* dcnt) {
    int i = blockIdx.x * blockDim.x + threadIdx.x;
    if (i < N_NODES) dcnt[i] = 0;
    if (i < N_GRAPHS * D_HID) pool[i] = 0.0f;
    if (i < D_HID) { bnsum[i] = 0.0f; bnsq[i] = 0.0f; }
    if (i < N_GRAPHS) cnt[i] = 0;
}

// ---------------- CSR scan ----------------
__global__ __launch_bounds__(1024) void k_scan(const int* __restrict__ dcnt,
                                               int* __restrict__ rowoff,
                                               int* __restrict__ wr) {
    __shared__ int wsum[32];
    int t = threadIdx.x;
    int lane = t & 31, w = t >> 5;
    const int CH = (N_NODES + 1023) / 1024;   // 49
    int lo = t * CH, hi = min(lo + CH, N_NODES);
    int s = 0;
    for (int i = lo; i < hi; i++) s += dcnt[i];
    int inc = s;
    #pragma unroll
    for (int o = 1; o < 32; o <<= 1) {
        int v = __shfl_up_sync(0xffffffffu, inc, o);
        if (lane >= o) inc += v;
    }
    if (lane == 31) wsum[w] = inc;
    __syncthreads();
    if (w == 0) {
        int v = (lane < 32) ? wsum[lane] : 0;
        int wi = v;
        #pragma unroll
        for (int o = 1; o < 32; o <<= 1) {
            int u = __shfl_up_sync(0xffffffffu, wi, o);
            if (lane >= o) wi += u;
        }
        wsum[lane] = wi - v;   // exclusive
        if (lane == 31) rowoff[N_NODES] = wi;
    }
    __syncthreads();
    int run = wsum[w] + inc - s;
    for (int i = lo; i < hi; i++) {
        rowoff[i] = run; wr[i] = run;
        run += dcnt[i];
    }
}

// ---- score helper: attn numerator for edge (s -> d), no max-shift ----
__device__ __forceinline__ float edge_ex(const float* __restrict__ as, float add, int s) {
    float e = __ldg(as + s) + add;
    e = (e > 0.f) ? e : NEG_SLOPE * e;
    return __expf(e);
}

// ------- fused GAT edge phase (layer 1): softmax + CSR aggregation -------
__global__ void k_agg_fused(const float* __restrict__ h, float* __restrict__ agg,
                            const int* __restrict__ rowoff, const int* __restrict__ srcid,
                            const float* __restrict__ as, const float* __restrict__ ad) {
    int d = (int)(((size_t)blockIdx.x * blockDim.x + threadIdx.x) >> 5);
    int lane = threadIdx.x & 31;
    if (d >= N_NODES) return;
    int beg = rowoff[d], end = rowoff[d + 1];
    float add = ad[d];
    float part = 0.f;
    for (int i = beg + lane; i < end; i += 32)
        part += edge_ex(as, add, srcid[i]);
    float invden = __frcp_rn(warp_red(part));
    float4 a0 = make_float4(0.f, 0.f, 0.f, 0.f);
    float4 a1 = make_float4(0.f, 0.f, 0.f, 0.f);
    for (int i = beg; i < end; i++) {
        int s = srcid[i];
        float attn = edge_ex(as, add, s) * invden;
        const float4* hs = (const float4*)(h + (size_t)s * D_HID);
        float4 v0 = hs[lane], v1 = hs[lane + 32];
        a0.x += attn * v0.x; a0.y += attn * v0.y; a0.z += attn * v0.z; a0.w += attn * v0.w;
        a1.x += attn * v1.x; a1.y += attn * v1.y; a1.z += attn * v1.z; a1.w += attn * v1.w;
    }
    float4* od = (float4*)(agg + (size_t)d * D_HID);
    od[lane] = a0;
    od[lane + 32] = a1;
}

// ------- fused edge phase (layer 2): softmax + agg + relu(+b2) + mean-pool -------
__global__ void k_agg_pool_fused(const float* __restrict__ h,
                                 const int* __restrict__ rowoff, const int* __restrict__ srcid,
                                 const float* __restrict__ as, const float* __restrict__ ad,
                                 const float* __restrict__ b2,
                                 const int* __restrict__ batch,
                                 float* __restrict__ pool) {
    int d = (int)(((size_t)blockIdx.x * blockDim.x + threadIdx.x) >> 5);
    int lane = threadIdx.x & 31;
    if (d >= N_NODES) return;
    int beg = rowoff[d], end = rowoff[d + 1];
    float add = ad[d];
    float part = 0.f;
    for (int i = beg + lane; i < end; i += 32)
        part += edge_ex(as, add, srcid[i]);
    float invden = __frcp_rn(warp_red(part));
    float4 a0 = make_float4(0.f, 0.f, 0.f, 0.f);
    float4 a1 = make_float4(0.f, 0.f, 0.f, 0.f);
    for (int i = beg; i < end; i++) {
        int s = srcid[i];
        float attn = edge_ex(as, add, s) * invden;
        const float4* hs = (const float4*)(h + (size_t)s * D_HID);
        float4 v0 = hs[lane], v1 = hs[lane + 32];
        a0.x += attn * v0.x; a0.y += attn * v0.y; a0.z += attn * v0.z; a0.w += attn * v0.w;
        a1.x += attn * v1.x; a1.y += attn * v1.y; a1.z += attn * v1.z; a1.w += attn * v1.w;
    }
    float4 b0 = ((const float4*)b2)[lane];
    float4 b1 = ((const float4*)b2)[lane + 32];
    a0.x = fmaxf(a0.x + b0.x, 0.f); a0.y = fmaxf(a0.y + b0.y, 0.f);
    a0.z = fmaxf(a0.z + b0.z, 0.f); a0.w = fmaxf(a0.w + b0.w, 0.f);
    a1.x = fmaxf(a1.x + b1.x, 0.f); a1.y = fmaxf(a1.y + b1.y, 0.f);
    a1.z = fmaxf(a1.z + b1.z, 0.f); a1.w = fmaxf(a1.w + b1.w, 0.f);
    int g = batch[d];
    float4* pg = (float4*)(pool + (size_t)g * D_HID);
    asm volatile("red.global.add.v4.f32 [%0], {%1,%2,%3,%4};"
                 :: "l"(pg + lane), "f"(a0.x), "f"(a0.y), "f"(a0.z), "f"(a0.w) : "memory");
    asm volatile("red.global.add.v4.f32 [%0], {%1,%2,%3,%4};"
                 :: "l"(pg + lane + 32), "f"(a1.x), "f"(a1.y), "f"(a1.z), "f"(a1.w) : "memory");
}

// ---------------- BatchNorm stats ----------------
#define ROWS_PER_BLK 64
__global__ void k_bnstats(const float* __restrict__ h, float* __restrict__ bsum,
                          float* __restrict__ bsq) {
    int col = threadIdx.x;
    int r0 = blockIdx.x * ROWS_PER_BLK;
    int r1 = min(r0 + ROWS_PER_BLK, N_NODES);
    float s = 0.f, q = 0.f;
    for (int r = r0; r < r1; r++) {
        float v = h[(size_t)r * D_HID + col];
        s += v; q += v * v;
    }
    atomicAdd(&bsum[col], s);
    atomicAdd(&bsq[col], q);
}

// ---------------- classifier ----------------
__global__ void k_clf(const float* __restrict__ pool, const int* __restrict__ cnt,
                      const float* __restrict__ claim, const float* __restrict__ W,
                      const float* __restrict__ bias, float* __restrict__ out) {
    __shared__ float red[256];
    int b = blockIdx.x;
    int t = threadIdx.x;
    float c = fmaxf((float)cnt[b], 1.0f);
    float part = (pool[b * D_HID + t] / c) * W[t];
    #pragma unroll
    for (int j = 0; j < 3; j++) {
        int k = t + j * 256;
        part += claim[(size_t)b * D_IN + k] * W[D_HID + k];
    }
    red[t] = part;
    __syncthreads();
    #pragma unroll
    for (int o = 128; o; o >>= 1) {
        if (t < o) red[t] += red[t + o];
        __syncthreads();
    }
    if (t == 0) out[b] = red[0] + bias[0];
}

// ---------------- host launcher ----------------
extern "C" void kernel_launch(void* const* d_in, const int* in_sizes, int n_in,
                              void* d_out, int out_size) {
    const float* claim   = (const float*)d_in[0];
    const float* x       = (const float*)d_in[1];
    const int*   ei      = (const int*)d_in[2];
    const int*   batch   = (const int*)d_in[3];
    const float* W1      = (const float*)d_in[4];
    const float* a_src1  = (const float*)d_in[5];
    const float* a_dst1  = (const float*)d_in[6];
    // d_in[7] = b1 : provably no-op through training-mode BatchNorm
    const float* W2      = (const float*)d_in[8];
    const float* a_src2  = (const float*)d_in[9];
    const float* a_dst2  = (const float*)d_in[10];
    const float* b2      = (const float*)d_in[11];
    const float* gamma   = (const float*)d_in[12];
    const float* beta    = (const float*)d_in[13];
    const float* clfW    = (const float*)d_in[14];
    const float* clfb    = (const float*)d_in[15];
    float* out = (float*)d_out;

    float *p_rel, *p_A, *p_B, *p_as, *p_ad, *p_bnsum, *p_bnsq, *p_pool;
    int *p_cnt, *p_dcnt, *p_rowoff, *p_wr, *p_srcid;
    unsigned char *p_w1h, *p_w1l, *p_w2h, *p_w2l;
    cudaGetSymbolAddress((void**)&p_rel, g_rel);
    cudaGetSymbolAddress((void**)&p_A, g_bufA);
    cudaGetSymbolAddress((void**)&p_B, g_bufB);
    cudaGetSymbolAddress((void**)&p_as, g_as);
    cudaGetSymbolAddress((void**)&p_ad, g_ad);
    cudaGetSymbolAddress((void**)&p_bnsum, g_bnsum);
    cudaGetSymbolAddress((void**)&p_bnsq, g_bnsq);
    cudaGetSymbolAddress((void**)&p_pool, g_pool);
    cudaGetSymbolAddress((void**)&p_cnt, g_cnt);
    cudaGetSymbolAddress((void**)&p_dcnt, g_dcnt);
    cudaGetSymbolAddress((void**)&p_rowoff, g_rowoff);
    cudaGetSymbolAddress((void**)&p_wr, g_wr);
    cudaGetSymbolAddress((void**)&p_srcid, g_srcid);
    cudaGetSymbolAddress((void**)&p_w1h, g_w1h);
    cudaGetSymbolAddress((void**)&p_w1l, g_w1l);
    cudaGetSymbolAddress((void**)&p_w2h, g_w2h);
    cudaGetSymbolAddress((void**)&p_w2l, g_w2l);

    cudaFuncSetAttribute(k_gemm_tc, cudaFuncAttributeMaxDynamicSharedMemorySize, SM_SZ);

    const int chunkBlocks = (N_NODES + ROWS_PER_BLK - 1) / ROWS_PER_BLK;
    const int gemmBlocks = (N_NODES + 127) / 128;

    // launch order: GEMM1 stays the 4th launch (ncu captures #4).
    k_zero_all<<<NODE_BLKS, 256>>>(p_bnsum, p_bnsq, p_pool, p_cnt, p_dcnt);
    k_misc1<<<WNODE_BLKS + EDGE_BLKS + PREP1_BLKS, 256>>>(
        claim, x, batch, p_rel, p_cnt, ei, p_dcnt, W1, p_w1h, p_w1l);
    k_scan<<<1, 1024>>>(p_dcnt, p_rowoff, p_wr);
    k_gemm_tc<<<gemmBlocks, 256, SM_SZ>>>(x, D_IN, p_w1h, p_w1l, p_A,
                                          p_rel, nullptr, nullptr, nullptr, nullptr,
                                          a_src1, a_dst1, p_as, p_ad, N_NODES);
    k_misc2<<<EDGE_BLKS + PREP2_BLKS, 256>>>(ei, p_wr, p_srcid, W2, p_w2h, p_w2l);

    // ---- layer 1: fused softmax + aggregation ----
    k_agg_fused<<<WNODE_BLKS, 256>>>(p_A, p_B, p_rowoff, p_srcid, p_as, p_ad);

    // ---- BN stats (finalize folded into GEMM2's loader) ----
    k_bnstats<<<chunkBlocks, 256>>>(p_B, p_bnsum, p_bnsq);

    // ---- layer 2: GEMM (BN+ReLU fused) + fused edge phase + pooling ----
    k_gemm_tc<<<gemmBlocks, 256, SM_SZ>>>(p_B, D_HID, p_w2h, p_w2l, p_A,
                                          nullptr, p_bnsum, p_bnsq, gamma, beta,
                                          a_src2, a_dst2, p_as, p_ad, N_NODES);
    k_agg_pool_fused<<<WNODE_BLKS, 256>>>(p_A, p_rowoff, p_srcid, p_as, p_ad,
                                          b2, batch, p_pool);

    // ---- classifier ----
    k_clf<<<N_GRAPHS, 256>>>(p_pool, p_cnt, claim, clfW, clfb, out);
}